// round 14
// baseline (speedup 1.0000x reference)
#include <cuda_runtime.h>
#include <cuda_fp16.h>
#include <cstdint>
#include <cstddef>

#define N_NODES 8192
#define N_EDGES 65536
#define CACHE_E 16
#define MAXDEG 256

// ================= scratch (device globals) =================
__device__ __half g_P_h[(size_t)N_NODES * 2048];   // [P1 | P3]
__device__ __half g_Q_h[(size_t)N_NODES * 1200];   // [Q1 | Q2]

// CSR by dst
__device__ int g_cnt[N_NODES];
__device__ int g_off[N_NODES];
__device__ int g_fill[N_NODES];
__device__ int g_eid[N_EDGES];

// fp16 operands
__device__ __half g_nf_h[(size_t)N_NODES * 1024];
__device__ __half g_w2v_h[(size_t)N_NODES * 320];
__device__ __half g_zf_h[(size_t)N_NODES * 1024];
__device__ __half g_zfl_h[(size_t)N_NODES * 320];
__device__ __half g_WeT_h[(size_t)2048 * 1024];
__device__ __half g_WnT_h[(size_t)2048 * 1024];
__device__ __half g_WelT_h[(size_t)1280 * 320];
__device__ __half g_WnlT_h[(size_t)768 * 320];

// ================= small helpers =================
__device__ __forceinline__ uint32_t smem_u32(const void* p) {
    uint32_t a;
    asm("{ .reg .u64 t; cvta.to.shared.u64 t, %1; cvt.u32.u64 %0, t; }" : "=r"(a) : "l"(p));
    return a;
}
__device__ __forceinline__ void cp16(uint32_t dst, const void* src) {
    asm volatile("cp.async.cg.shared.global [%0], [%1], 16;" :: "r"(dst), "l"(src) : "memory");
}
__device__ __forceinline__ void cp8(uint32_t dst, const void* src) {
    asm volatile("cp.async.ca.shared.global [%0], [%1], 8;" :: "r"(dst), "l"(src) : "memory");
}
__device__ __forceinline__ void cp_commit() {
    asm volatile("cp.async.commit_group;" ::: "memory");
}
__device__ __forceinline__ void cp_wait_all() {
    asm volatile("cp.async.wait_group 0;" ::: "memory");
}
__device__ __forceinline__ void ldmx4(uint32_t* r, uint32_t addr) {
    asm volatile("ldmatrix.sync.aligned.m8n8.x4.shared.b16 {%0,%1,%2,%3}, [%4];"
                 : "=r"(r[0]), "=r"(r[1]), "=r"(r[2]), "=r"(r[3]) : "r"(addr));
}
__device__ __forceinline__ void mma_f16(float* c, const uint32_t* a, const uint32_t* b) {
    asm volatile(
        "mma.sync.aligned.m16n8k16.row.col.f32.f16.f16.f32 "
        "{%0,%1,%2,%3}, {%4,%5,%6,%7}, {%8,%9}, {%0,%1,%2,%3};"
        : "+f"(c[0]), "+f"(c[1]), "+f"(c[2]), "+f"(c[3])
        : "r"(a[0]), "r"(a[1]), "r"(a[2]), "r"(a[3]), "r"(b[0]), "r"(b[1]));
}
__device__ __forceinline__ float4 h4_to_f4(uint2 pk) {
    __half2 h0 = *(__half2*)&pk.x;
    __half2 h1 = *(__half2*)&pk.y;
    float2 f0 = __half22float2(h0);
    float2 f1 = __half22float2(h1);
    return make_float4(f0.x, f0.y, f1.x, f1.y);
}

// ================= batched fp16 HMMA GEMM (unchanged, known-good) =================
#define KC 64
#define TILE_B 16384
#define STAGE_B (2 * TILE_B)
#define GEMM_SMEM (2 * STAGE_B)

struct GemmJob {
    float* C; __half* Ch; int ldc; int Nvalid;
    const __half* A1; const __half* B1; int K1;
    const __half* A2; const __half* B2; int K2;
    const float* bias; int do_relu; int bx;
};

__device__ __forceinline__ void issue_chunk(
    uint32_t sb_stage,
    const __half* A, const __half* B,
    int ldA, int ldB, int rowBase, int colBase, int k0, int tid)
{
#pragma unroll
    for (int t = 0; t < 2; ++t) {
        const __half* src = (t == 0) ? A : B;
        const int row0 = (t == 0) ? rowBase : colBase;
        const int ld = (t == 0) ? ldA : ldB;
        const uint32_t tb = sb_stage + t * TILE_B;
#pragma unroll
        for (int i = 0; i < 4; ++i) {
            int idx = i * 256 + tid;
            int r = idx >> 3;
            int cch = idx & 7;
            uint32_t dst = tb + r * 128 + (((cch ^ (r & 7))) << 4);
            cp16(dst, src + (size_t)(row0 + r) * ld + k0 + cch * 8);
        }
    }
}

__global__ __launch_bounds__(256, 2) void mma_gemm(GemmJob j0, GemmJob j1)
{
    const GemmJob j = (blockIdx.z == 0) ? j0 : j1;
    if ((int)blockIdx.x >= j.bx) return;

    extern __shared__ char smem[];
    const uint32_t sb = smem_u32(smem);
    const int tid = threadIdx.x;
    const int wid = tid >> 5;
    const int lane = tid & 31;
    const int warp_m = wid & 3;
    const int warp_n = wid >> 2;
    const int rowBase = blockIdx.y * 128;
    const int colBase = blockIdx.x * 128;

    float c[2][8][4];
#pragma unroll
    for (int i = 0; i < 2; ++i)
#pragma unroll
        for (int jn = 0; jn < 8; ++jn)
#pragma unroll
            for (int k = 0; k < 4; ++k) c[i][jn][k] = 0.f;

    const int NC1 = j.K1 / KC;
    const int NC2 = j.K2 / KC;
    const int NC = NC1 + NC2;

    issue_chunk(sb, j.A1, j.B1, j.K1, j.K1, rowBase, colBase, 0, tid);
    cp_commit();

#pragma unroll 1
    for (int ch = 0; ch < NC; ++ch) {
        const uint32_t cur = sb + (uint32_t)(ch & 1) * STAGE_B;
        if (ch + 1 < NC) {
            int nc = ch + 1;
            if (nc < NC1)
                issue_chunk(sb + (uint32_t)(nc & 1) * STAGE_B, j.A1, j.B1,
                            j.K1, j.K1, rowBase, colBase, nc * KC, tid);
            else
                issue_chunk(sb + (uint32_t)(nc & 1) * STAGE_B, j.A2, j.B2,
                            j.K2, j.K2, rowBase, colBase, (nc - NC1) * KC, tid);
            cp_commit();
            asm volatile("cp.async.wait_group 1;" ::: "memory");
        } else {
            cp_wait_all();
        }
        __syncthreads();

#pragma unroll
        for (int ks = 0; ks < 4; ++ks) {
            uint32_t ah[2][4], bh[4][4];
#pragma unroll
            for (int mf = 0; mf < 2; ++mf) {
                int row = warp_m * 32 + mf * 16 + ((lane >> 3) & 1) * 8 + (lane & 7);
                int chunk = ks * 2 + (lane >> 4);
                uint32_t ad = cur + row * 128 + ((chunk ^ (row & 7)) << 4);
                ldmx4(ah[mf], ad);
            }
#pragma unroll
            for (int nf2 = 0; nf2 < 4; ++nf2) {
                int row = warp_n * 64 + nf2 * 16 + (lane >> 4) * 8 + (lane & 7);
                int chunk = ks * 2 + ((lane >> 3) & 1);
                uint32_t bd = cur + TILE_B + row * 128 + ((chunk ^ (row & 7)) << 4);
                ldmx4(bh[nf2], bd);
            }
#pragma unroll
            for (int mf = 0; mf < 2; ++mf)
#pragma unroll
                for (int nf = 0; nf < 8; ++nf)
                    mma_f16(c[mf][nf], ah[mf], &bh[nf >> 1][(nf & 1) * 2]);
        }
        __syncthreads();
    }

    const int r0 = rowBase + warp_m * 32 + (lane >> 2);
    const int colb = colBase + warp_n * 64 + (lane & 3) * 2;
#pragma unroll
    for (int mf = 0; mf < 2; ++mf) {
        int row = r0 + mf * 16;
#pragma unroll
        for (int nf = 0; nf < 8; ++nf) {
            int col = colb + nf * 8;
            if (col < j.Nvalid) {
                float b0 = 0.f, b1 = 0.f;
                if (j.bias) { b0 = j.bias[col]; b1 = j.bias[col + 1]; }
                float2 v0, v1;
                v0.x = c[mf][nf][0] + b0; v0.y = c[mf][nf][1] + b1;
                v1.x = c[mf][nf][2] + b0; v1.y = c[mf][nf][3] + b1;
                if (j.do_relu) {
                    v0.x = fmaxf(v0.x, 0.f); v0.y = fmaxf(v0.y, 0.f);
                    v1.x = fmaxf(v1.x, 0.f); v1.y = fmaxf(v1.y, 0.f);
                }
                if (j.Ch) {
                    __half2 h0 = __floats2half2_rn(v0.x, v0.y);
                    __half2 h1 = __floats2half2_rn(v1.x, v1.y);
                    *(__half2*)(j.Ch + (size_t)row * j.ldc + col) = h0;
                    *(__half2*)(j.Ch + (size_t)(row + 8) * j.ldc + col) = h1;
                } else {
                    *(float2*)(j.C + (size_t)row * j.ldc + col) = v0;
                    *(float2*)(j.C + (size_t)(row + 8) * j.ldc + col) = v1;
                }
            }
        }
    }
}

// ================= conversion kernels (merged; also zeroes g_cnt) =================
__global__ void round_rows2(const float* __restrict__ a, __half* __restrict__ ah,
                            const float* __restrict__ b, __half* __restrict__ bh) {
    const size_t T1 = (size_t)N_NODES * 1024;
    const size_t T2 = (size_t)N_NODES * 320;
    size_t gid = (size_t)blockIdx.x * blockDim.x + threadIdx.x;
    size_t stride = (size_t)gridDim.x * blockDim.x;
    for (size_t i = gid; i < (size_t)N_NODES; i += stride) g_cnt[i] = 0;
    for (size_t i = gid; i < T1 + T2; i += stride) {
        if (i < T1) {
            ah[i] = __float2half_rn(a[i]);
        } else {
            size_t jj = i - T1;
            int row = (int)(jj / 320);
            int col = (int)(jj % 320);
            float v = (col < 300) ? b[(size_t)row * 300 + col] : 0.f;
            bh[jj] = __float2half_rn(v);
        }
    }
}

__global__ void transpose_round2(const float* __restrict__ W0, const float* __restrict__ W1,
                                 int ldw, int K, int N,
                                 __half* __restrict__ hi, int Kd, int n0_0, int n0_1) {
    const float* W = blockIdx.z ? W1 : W0;
    const int n0 = blockIdx.z ? n0_1 : n0_0;
    __shared__ float tile[32][33];
    int kb = blockIdx.y * 32, nb = blockIdx.x * 32;
#pragma unroll
    for (int i = 0; i < 4; ++i) {
        int k = kb + threadIdx.y + i * 8;
        int n = nb + threadIdx.x;
        tile[threadIdx.y + i * 8][threadIdx.x] = (k < K && n < N) ? W[(size_t)k * ldw + n] : 0.f;
    }
    __syncthreads();
#pragma unroll
    for (int i = 0; i < 4; ++i) {
        int n = nb + threadIdx.y + i * 8;
        int k = kb + threadIdx.x;
        if (n < N && k < Kd)
            hi[(size_t)(n0 + n) * Kd + k] = __float2half_rn(tile[threadIdx.x][threadIdx.y + i * 8]);
    }
}

// ================= CSR construction =================
__global__ void hist_kernel(const int* __restrict__ dst) {
    int e = blockIdx.x * blockDim.x + threadIdx.x;
    if (e < N_EDGES) atomicAdd(&g_cnt[dst[e]], 1);
}
__global__ __launch_bounds__(1024) void scan_kernel() {
    __shared__ int sm[1024];
    int t = threadIdx.x;
    int loc[8];
    int s = 0;
#pragma unroll
    for (int i = 0; i < 8; ++i) { loc[i] = g_cnt[t * 8 + i]; s += loc[i]; }
    sm[t] = s;
    __syncthreads();
    for (int off = 1; off < 1024; off <<= 1) {
        int v = sm[t];
        if (t >= off) v += sm[t - off];
        __syncthreads();
        sm[t] = v;
        __syncthreads();
    }
    int run = (t == 0) ? 0 : sm[t - 1];
#pragma unroll
    for (int i = 0; i < 8; ++i) {
        g_off[t * 8 + i] = run;
        g_fill[t * 8 + i] = run;
        run += loc[i];
    }
}
__global__ void fill_kernel(const int* __restrict__ dst) {
    int e = blockIdx.x * blockDim.x + threadIdx.x;
    if (e < N_EDGES) {
        int pos = atomicAdd(&g_fill[dst[e]], 1);
        g_eid[pos] = e;
    }
}

// ================= merged score+softmax+combine kernel =================
#define COMB_SMEM ((2 * CACHE_E * 1024 + CACHE_E * 320) * 2)

__global__ __launch_bounds__(256) void combine_all(
    const float* __restrict__ n_f, const float* __restrict__ w2v,
    const float* __restrict__ s_f, const int* __restrict__ src,
    const float* __restrict__ We, const float* __restrict__ be,
    const float* __restrict__ Wa,
    const float* __restrict__ bel, const float* __restrict__ Wal)
{
    extern __shared__ __half dyn[];
    __half* efc = dyn;
    __half* nfc = dyn + CACHE_E * 1024;
    __half* wvc = dyn + 2 * CACHE_E * 1024;
    const uint32_t efc_b = smem_u32(efc);
    const uint32_t nfc_b = smem_u32(nfc);
    const uint32_t wvc_b = smem_u32(wvc);

    const int d = blockIdx.x;
    const int t = threadIdx.x;
    const int lane = t & 31;
    const int deg = g_cnt[d];
    const int start = g_off[d];
    const int cdeg = (deg < CACHE_E) ? deg : CACHE_E;

    __shared__ int sm_eid[MAXDEG], sm_src[MAXDEG];
    __shared__ float sm_af[MAXDEG], sm_afl[MAXDEG];
    __shared__ float sm_scal[4];

    for (int i = t; i < deg; i += 256) {
        int e = g_eid[start + i];
        sm_eid[i] = e;
        sm_src[i] = src[e];
    }
    for (int i = t; i < MAXDEG; i += 256) { sm_af[i] = 0.f; sm_afl[i] = 0.f; }
    __syncthreads();

    // ---------- Phase A0: bulk-gather P rows (full MLP) ----------
#pragma unroll 1
    for (int i = 0; i < cdeg; ++i)
        cp8(efc_b + (uint32_t)(i * 1024 + 4 * t) * 2,
            g_P_h + (size_t)sm_src[i] * 2048 + 4 * t);
    cp_commit();

    const float4* Ws4 = (const float4*)(We + (size_t)1024 * 1024);
    float4 wsr[16];
#pragma unroll
    for (int k = 0; k < 16; ++k) wsr[k] = Ws4[k * 256 + t];

    float4 p3r;
    {
        uint2 pr = *(const uint2*)(g_P_h + (size_t)d * 2048 + 1024 + 4 * t);
        p3r = h4_to_f4(pr);
        float4 ber = ((const float4*)be)[t];
        p3r.x += ber.x; p3r.y += ber.y; p3r.z += ber.z; p3r.w += ber.w;
    }
    float4 war = ((const float4*)Wa)[t];

    cp_wait_all();
    __syncthreads();

    // ---------- Phase A1: e_f + main scores, 2 edges per iteration ----------
#pragma unroll 1
    for (int i = 0; i < deg; i += 2) {
        const bool two = (i + 1 < deg);
        const int eA = sm_eid[i];
        const int eB = two ? sm_eid[i + 1] : eA;

        const float4* sfA4 = (const float4*)(s_f + (size_t)eA * 16);
        const float4* sfB4 = (const float4*)(s_f + (size_t)eB * 16);
        float4 sA0 = __ldg(sfA4 + 0), sA1 = __ldg(sfA4 + 1),
               sA2 = __ldg(sfA4 + 2), sA3 = __ldg(sfA4 + 3);
        float4 sB0 = __ldg(sfB4 + 0), sB1 = __ldg(sfB4 + 1),
               sB2 = __ldg(sfB4 + 2), sB3 = __ldg(sfB4 + 3);

        uint2 prA = (i < CACHE_E)
            ? *(const uint2*)(efc + i * 1024 + 4 * t)
            : *(const uint2*)(g_P_h + (size_t)sm_src[i] * 2048 + 4 * t);
        uint2 prB = prA;
        if (two)
            prB = (i + 1 < CACHE_E)
                ? *(const uint2*)(efc + (i + 1) * 1024 + 4 * t)
                : *(const uint2*)(g_P_h + (size_t)sm_src[i + 1] * 2048 + 4 * t);

        float4 vA = h4_to_f4(prA);
        vA.x += p3r.x; vA.y += p3r.y; vA.z += p3r.z; vA.w += p3r.w;
        float4 vB = h4_to_f4(prB);
        vB.x += p3r.x; vB.y += p3r.y; vB.z += p3r.z; vB.w += p3r.w;

        float fA[16] = {sA0.x, sA0.y, sA0.z, sA0.w, sA1.x, sA1.y, sA1.z, sA1.w,
                        sA2.x, sA2.y, sA2.z, sA2.w, sA3.x, sA3.y, sA3.z, sA3.w};
        float fB[16] = {sB0.x, sB0.y, sB0.z, sB0.w, sB1.x, sB1.y, sB1.z, sB1.w,
                        sB2.x, sB2.y, sB2.z, sB2.w, sB3.x, sB3.y, sB3.z, sB3.w};
#pragma unroll
        for (int k = 0; k < 16; ++k) {
            vA.x = fmaf(fA[k], wsr[k].x, vA.x); vA.y = fmaf(fA[k], wsr[k].y, vA.y);
            vA.z = fmaf(fA[k], wsr[k].z, vA.z); vA.w = fmaf(fA[k], wsr[k].w, vA.w);
            vB.x = fmaf(fB[k], wsr[k].x, vB.x); vB.y = fmaf(fB[k], wsr[k].y, vB.y);
            vB.z = fmaf(fB[k], wsr[k].z, vB.z); vB.w = fmaf(fB[k], wsr[k].w, vB.w);
        }
        vA.x = fmaxf(vA.x, 0.f); vA.y = fmaxf(vA.y, 0.f);
        vA.z = fmaxf(vA.z, 0.f); vA.w = fmaxf(vA.w, 0.f);
        vB.x = fmaxf(vB.x, 0.f); vB.y = fmaxf(vB.y, 0.f);
        vB.z = fmaxf(vB.z, 0.f); vB.w = fmaxf(vB.w, 0.f);

        if (i < CACHE_E) {
            __half2 h0 = __floats2half2_rn(vA.x, vA.y);
            __half2 h1 = __floats2half2_rn(vA.z, vA.w);
            uint2 pk; pk.x = *(uint32_t*)&h0; pk.y = *(uint32_t*)&h1;
            *(uint2*)(efc + i * 1024 + 4 * t) = pk;
        }
        if (two && (i + 1) < CACHE_E) {
            __half2 h0 = __floats2half2_rn(vB.x, vB.y);
            __half2 h1 = __floats2half2_rn(vB.z, vB.w);
            uint2 pk; pk.x = *(uint32_t*)&h0; pk.y = *(uint32_t*)&h1;
            *(uint2*)(efc + (i + 1) * 1024 + 4 * t) = pk;
        }

        float accA = vA.x * war.x + vA.y * war.y + vA.z * war.z + vA.w * war.w;
        float accB = two ? (vB.x * war.x + vB.y * war.y + vB.z * war.z + vB.w * war.w) : 0.f;

#pragma unroll
        for (int off = 16; off > 0; off >>= 1) {
            accA += __shfl_down_sync(0xffffffffu, accA, off);
            accB += __shfl_down_sync(0xffffffffu, accB, off);
        }
        if (lane == 0) {
            atomicAdd(&sm_af[i], accA);
            if (two) atomicAdd(&sm_af[i + 1], accB);
        }
    }

    // ---------- Phase A2: lang scores, 2 edges per iteration ----------
    {
        float4 q2r = make_float4(0.f, 0.f, 0.f, 0.f);
        float4 walr = make_float4(0.f, 0.f, 0.f, 0.f);
        if (t < 150) {
            uint2 qr = *(const uint2*)(g_Q_h + (size_t)d * 1200 + 600 + 4 * t);
            q2r = h4_to_f4(qr);
            float4 belr = ((const float4*)bel)[t];
            q2r.x += belr.x; q2r.y += belr.y; q2r.z += belr.z; q2r.w += belr.w;
            walr = ((const float4*)Wal)[t];
        }
#pragma unroll 1
        for (int i = 0; i < deg; i += 2) {
            const bool two = (i + 1 < deg);
            float accA = 0.f, accB = 0.f;
            if (t < 150) {
                uint2 qA = *(const uint2*)(g_Q_h + (size_t)sm_src[i] * 1200 + 4 * t);
                uint2 qB = qA;
                if (two) qB = *(const uint2*)(g_Q_h + (size_t)sm_src[i + 1] * 1200 + 4 * t);
                float4 uA = h4_to_f4(qA);
                uA.x = fmaxf(uA.x + q2r.x, 0.f); uA.y = fmaxf(uA.y + q2r.y, 0.f);
                uA.z = fmaxf(uA.z + q2r.z, 0.f); uA.w = fmaxf(uA.w + q2r.w, 0.f);
                accA = uA.x * walr.x + uA.y * walr.y + uA.z * walr.z + uA.w * walr.w;
                if (two) {
                    float4 uB = h4_to_f4(qB);
                    uB.x = fmaxf(uB.x + q2r.x, 0.f); uB.y = fmaxf(uB.y + q2r.y, 0.f);
                    uB.z = fmaxf(uB.z + q2r.z, 0.f); uB.w = fmaxf(uB.w + q2r.w, 0.f);
                    accB = uB.x * walr.x + uB.y * walr.y + uB.z * walr.z + uB.w * walr.w;
                }
            }
#pragma unroll
            for (int off = 16; off > 0; off >>= 1) {
                accA += __shfl_down_sync(0xffffffffu, accA, off);
                accB += __shfl_down_sync(0xffffffffu, accB, off);
            }
            if (lane == 0 && accA != 0.f) atomicAdd(&sm_afl[i], accA);
            if (lane == 0 && two && accB != 0.f) atomicAdd(&sm_afl[i + 1], accB);
        }
    }

    // ---------- Phase B0: bulk-gather nf / w2v rows (overlaps softmax) ----------
#pragma unroll 1
    for (int i = 0; i < cdeg; ++i) {
        int s = sm_src[i];
        cp8(nfc_b + (uint32_t)(i * 1024 + 4 * t) * 2,
            g_nf_h + (size_t)s * 1024 + 4 * t);
        if (t < 75)
            cp8(wvc_b + (uint32_t)(i * 320 + 4 * t) * 2,
                g_w2v_h + (size_t)s * 320 + 4 * t);
    }
    cp_commit();
    __syncthreads();

    // ---------- softmax scalars (warp 0) ----------
    if (t < 32) {
        float m = -1e30f, ml = -1e30f;
        for (int i = t; i < deg; i += 32) {
            m = fmaxf(m, sm_af[i]);
            ml = fmaxf(ml, sm_afl[i]);
        }
#pragma unroll
        for (int off = 16; off > 0; off >>= 1) {
            m = fmaxf(m, __shfl_xor_sync(0xffffffffu, m, off));
            ml = fmaxf(ml, __shfl_xor_sync(0xffffffffu, ml, off));
        }
        float den = 0.f, denl = 0.f;
        for (int i = t; i < deg; i += 32) {
            den += expf(sm_af[i] - m);
            denl += expf(sm_afl[i] - ml);
        }
#pragma unroll
        for (int off = 16; off > 0; off >>= 1) {
            den += __shfl_xor_sync(0xffffffffu, den, off);
            denl += __shfl_xor_sync(0xffffffffu, denl, off);
        }
        if (t == 0) {
            sm_scal[0] = m;
            sm_scal[1] = (deg > 0) ? 1.f / den : 0.f;
            sm_scal[2] = ml;
            sm_scal[3] = (deg > 0) ? 1.f / denl : 0.f;
        }
    }
    __syncthreads();

    {
        const float m = sm_scal[0], rden = sm_scal[1];
        const float ml = sm_scal[2], rdenl = sm_scal[3];
        for (int i = t; i < deg; i += 256) {
            sm_af[i] = expf(sm_af[i] - m) * rden;
            sm_afl[i] = expf(sm_afl[i] - ml) * rdenl;
        }
    }
    cp_wait_all();
    __syncthreads();

    // ---------- Phase B: weighted accumulate (smem-resident) ----------
    float4 acc = make_float4(0.f, 0.f, 0.f, 0.f);
    float4 accl = make_float4(0.f, 0.f, 0.f, 0.f);

#pragma unroll 1
    for (int i = 0; i < deg; ++i) {
        const float alpha = sm_af[i];
        const float alphal = sm_afl[i];

        float4 v, n;
        if (i < CACHE_E) {
            v = h4_to_f4(*(const uint2*)(efc + i * 1024 + 4 * t));
            n = h4_to_f4(*(const uint2*)(nfc + i * 1024 + 4 * t));
        } else {
            const int s = sm_src[i];
            const int eid = sm_eid[i];
            uint2 pr = *(const uint2*)(g_P_h + (size_t)s * 2048 + 4 * t);
            v = h4_to_f4(pr);
            v.x += p3r.x; v.y += p3r.y; v.z += p3r.z; v.w += p3r.w;
            const float4* sf4 = (const float4*)(s_f + (size_t)eid * 16);
            float4 sv0 = __ldg(sf4 + 0), sv1 = __ldg(sf4 + 1);
            float4 sv2 = __ldg(sf4 + 2), sv3 = __ldg(sf4 + 3);
            float sfs[16] = {sv0.x, sv0.y, sv0.z, sv0.w, sv1.x, sv1.y, sv1.z, sv1.w,
                             sv2.x, sv2.y, sv2.z, sv2.w, sv3.x, sv3.y, sv3.z, sv3.w};
#pragma unroll
            for (int k = 0; k < 16; ++k) {
                v.x = fmaf(sfs[k], wsr[k].x, v.x); v.y = fmaf(sfs[k], wsr[k].y, v.y);
                v.z = fmaf(sfs[k], wsr[k].z, v.z); v.w = fmaf(sfs[k], wsr[k].w, v.w);
            }
            v.x = fmaxf(v.x, 0.f); v.y = fmaxf(v.y, 0.f);
            v.z = fmaxf(v.z, 0.f); v.w = fmaxf(v.w, 0.f);
            n = h4_to_f4(*(const uint2*)(g_nf_h + (size_t)s * 1024 + 4 * t));
        }

        acc.x = fmaf(alpha, n.x + v.x, acc.x);
        acc.y = fmaf(alpha, n.y + v.y, acc.y);
        acc.z = fmaf(alpha, n.z + v.z, acc.z);
        acc.w = fmaf(alpha, n.w + v.w, acc.w);

        if (t < 75) {
            float4 w;
            if (i < CACHE_E)
                w = h4_to_f4(*(const uint2*)(wvc + i * 320 + 4 * t));
            else
                w = h4_to_f4(*(const uint2*)(g_w2v_h + (size_t)sm_src[i] * 320 + 4 * t));
            accl.x = fmaf(alphal, w.x, accl.x);
            accl.y = fmaf(alphal, w.y, accl.y);
            accl.z = fmaf(alphal, w.z, accl.z);
            accl.w = fmaf(alphal, w.w, accl.w);
        }
    }

    // ---------- write fp16 ----------
    {
        size_t o = (size_t)d * 1024 + 4 * t;
        g_zf_h[o + 0] = __float2half_rn(acc.x);
        g_zf_h[o + 1] = __float2half_rn(acc.y);
        g_zf_h[o + 2] = __float2half_rn(acc.z);
        g_zf_h[o + 3] = __float2half_rn(acc.w);
    }
    if (t < 75) {
        size_t o = (size_t)d * 320 + 4 * t;
        g_zfl_h[o + 0] = __float2half_rn(accl.x);
        g_zfl_h[o + 1] = __float2half_rn(accl.y);
        g_zfl_h[o + 2] = __float2half_rn(accl.z);
        g_zfl_h[o + 3] = __float2half_rn(accl.w);
    }
}

// ================= launch =================
extern "C" void kernel_launch(void* const* d_in, const int* in_sizes, int n_in,
                              void* d_out, int out_size) {
    const float* n_f  = (const float*)d_in[0];
    const float* w2v  = (const float*)d_in[1];
    const float* s_f  = (const float*)d_in[2];
    const int*   src  = (const int*)d_in[3];
    const int*   dst  = (const int*)d_in[4];
    const float* We   = (const float*)d_in[5];
    const float* be   = (const float*)d_in[6];
    const float* Wel  = (const float*)d_in[7];
    const float* bel  = (const float*)d_in[8];
    const float* Wa   = (const float*)d_in[9];
    const float* Wal  = (const float*)d_in[11];
    const float* Wn   = (const float*)d_in[13];
    const float* bn   = (const float*)d_in[14];
    const float* Wnl  = (const float*)d_in[15];
    const float* bnl  = (const float*)d_in[16];

    float* out      = (float*)d_out;
    float* out_lang = out + (size_t)N_NODES * 1024;

    __half *P_h, *Q_h;
    __half *nf_h, *w2v_h, *zf_h, *zfl_h;
    __half *WeT_h, *WnT_h, *WelT_h, *WnlT_h;
    cudaGetSymbolAddress((void**)&P_h, g_P_h);
    cudaGetSymbolAddress((void**)&Q_h, g_Q_h);
    cudaGetSymbolAddress((void**)&nf_h, g_nf_h);
    cudaGetSymbolAddress((void**)&w2v_h, g_w2v_h);
    cudaGetSymbolAddress((void**)&zf_h, g_zf_h);
    cudaGetSymbolAddress((void**)&zfl_h, g_zfl_h);
    cudaGetSymbolAddress((void**)&WeT_h, g_WeT_h);
    cudaGetSymbolAddress((void**)&WnT_h, g_WnT_h);
    cudaGetSymbolAddress((void**)&WelT_h, g_WelT_h);
    cudaGetSymbolAddress((void**)&WnlT_h, g_WnlT_h);

    cudaFuncSetAttribute(mma_gemm, cudaFuncAttributeMaxDynamicSharedMemorySize, GEMM_SMEM);
    cudaFuncSetAttribute(combine_all, cudaFuncAttributeMaxDynamicSharedMemorySize, COMB_SMEM);

    dim3 tblk(32, 8);

    round_rows2<<<2048, 256>>>(n_f, nf_h, w2v, w2v_h);   // also zeroes g_cnt
    transpose_round2<<<dim3(32, 32, 2), tblk>>>(We, We + (size_t)1040 * 1024,
                                                1024, 1024, 1024, WeT_h, 1024, 0, 1024);
    transpose_round2<<<dim3(19, 10, 2), tblk>>>(Wel, Wel + (size_t)300 * 600,
                                                600, 300, 600, WelT_h, 320, 0, 600);
    hist_kernel<<<64, 1024>>>(dst);
    scan_kernel<<<1, 1024>>>();
    fill_kernel<<<64, 1024>>>(dst);

    // batched projections: z=0 -> P, z=1 -> Q
    {
        GemmJob jp = {nullptr, P_h, 2048, 2048, nf_h, WeT_h, 1024,
                      nullptr, nullptr, 0, nullptr, 0, 16};
        GemmJob jq = {nullptr, Q_h, 1200, 1200, w2v_h, WelT_h, 320,
                      nullptr, nullptr, 0, nullptr, 0, 10};
        mma_gemm<<<dim3(16, 64, 2), 256, GEMM_SMEM>>>(jp, jq);
    }

    transpose_round2<<<dim3(32, 32, 2), tblk>>>(Wn, Wn + (size_t)1024 * 1024,
                                                1024, 1024, 1024, WnT_h, 1024, 0, 1024);
    transpose_round2<<<dim3(10, 10, 2), tblk>>>(Wnl, Wnl + (size_t)300 * 300,
                                                300, 300, 300, WnlT_h, 320, 0, 300);

    combine_all<<<N_NODES, 256, COMB_SMEM>>>(
        n_f, w2v, s_f, src, We, be, Wa, bel, Wal);

    // batched node-apply: z=0 -> out, z=1 -> out_lang
    {
        GemmJob jo = {out, nullptr, 1024, 1024, nf_h, WnT_h, 1024,
                      zf_h, WnT_h + (size_t)1024 * 1024, 1024, bn, 1, 8};
        GemmJob jl = {out_lang, nullptr, 300, 300, w2v_h, WnlT_h, 320,
                      zfl_h, WnlT_h + (size_t)300 * 320, 320, bnl, 1, 3};
        mma_gemm<<<dim3(8, 64, 2), 256, GEMM_SMEM>>>(jo, jl);
    }
}

// round 15
// speedup vs baseline: 1.0503x; 1.0503x over previous
#include <cuda_runtime.h>
#include <cuda_fp16.h>
#include <cstdint>
#include <cstddef>

#define N_NODES 8192
#define N_EDGES 65536
#define CACHE_E 16
#define MAXDEG 256

// ================= scratch (device globals) =================
__device__ __half g_P_h[(size_t)N_NODES * 2048];   // [P1 | P3]
__device__ __half g_Q_h[(size_t)N_NODES * 1200];   // [Q1 | Q2]

// CSR by dst
__device__ int g_cnt[N_NODES];
__device__ int g_off[N_NODES];
__device__ int g_fill[N_NODES];
__device__ int g_eid[N_EDGES];

// fp16 operands
__device__ __half g_nf_h[(size_t)N_NODES * 1024];
__device__ __half g_w2v_h[(size_t)N_NODES * 320];
__device__ __half g_zf_h[(size_t)N_NODES * 1024];
__device__ __half g_zfl_h[(size_t)N_NODES * 320];
__device__ __half g_WeT_h[(size_t)2048 * 1024];
__device__ __half g_WnT_h[(size_t)2048 * 1024];
__device__ __half g_WelT_h[(size_t)1280 * 320];
__device__ __half g_WnlT_h[(size_t)768 * 320];

// ================= small helpers =================
__device__ __forceinline__ uint32_t smem_u32(const void* p) {
    uint32_t a;
    asm("{ .reg .u64 t; cvta.to.shared.u64 t, %1; cvt.u32.u64 %0, t; }" : "=r"(a) : "l"(p));
    return a;
}
__device__ __forceinline__ void cp16(uint32_t dst, const void* src) {
    asm volatile("cp.async.cg.shared.global [%0], [%1], 16;" :: "r"(dst), "l"(src) : "memory");
}
__device__ __forceinline__ void cp8(uint32_t dst, const void* src) {
    asm volatile("cp.async.ca.shared.global [%0], [%1], 8;" :: "r"(dst), "l"(src) : "memory");
}
__device__ __forceinline__ void cp_commit() {
    asm volatile("cp.async.commit_group;" ::: "memory");
}
__device__ __forceinline__ void cp_wait_all() {
    asm volatile("cp.async.wait_group 0;" ::: "memory");
}
__device__ __forceinline__ void ldmx4(uint32_t* r, uint32_t addr) {
    asm volatile("ldmatrix.sync.aligned.m8n8.x4.shared.b16 {%0,%1,%2,%3}, [%4];"
                 : "=r"(r[0]), "=r"(r[1]), "=r"(r[2]), "=r"(r[3]) : "r"(addr));
}
__device__ __forceinline__ void mma_f16(float* c, const uint32_t* a, const uint32_t* b) {
    asm volatile(
        "mma.sync.aligned.m16n8k16.row.col.f32.f16.f16.f32 "
        "{%0,%1,%2,%3}, {%4,%5,%6,%7}, {%8,%9}, {%0,%1,%2,%3};"
        : "+f"(c[0]), "+f"(c[1]), "+f"(c[2]), "+f"(c[3])
        : "r"(a[0]), "r"(a[1]), "r"(a[2]), "r"(a[3]), "r"(b[0]), "r"(b[1]));
}
__device__ __forceinline__ float4 h4_to_f4(uint2 pk) {
    __half2 h0 = *(__half2*)&pk.x;
    __half2 h1 = *(__half2*)&pk.y;
    float2 f0 = __half22float2(h0);
    float2 f1 = __half22float2(h1);
    return make_float4(f0.x, f0.y, f1.x, f1.y);
}

// ================= batched fp16 HMMA GEMM =================
#define KC 64
#define TILE_B 16384
#define STAGE_B (2 * TILE_B)
#define GEMM_SMEM (2 * STAGE_B)

struct GemmJob {
    float* C; __half* Ch; int ldc; int Nvalid;
    const __half* A1; const __half* B1; int K1;
    const __half* A2; const __half* B2; int K2;
    const float* bias; int do_relu; int bx;
};

__device__ __forceinline__ void issue_chunk(
    uint32_t sb_stage,
    const __half* A, const __half* B,
    int ldA, int ldB, int rowBase, int colBase, int k0, int tid)
{
#pragma unroll
    for (int t = 0; t < 2; ++t) {
        const __half* src = (t == 0) ? A : B;
        const int row0 = (t == 0) ? rowBase : colBase;
        const int ld = (t == 0) ? ldA : ldB;
        const uint32_t tb = sb_stage + t * TILE_B;
#pragma unroll
        for (int i = 0; i < 4; ++i) {
            int idx = i * 256 + tid;
            int r = idx >> 3;
            int cch = idx & 7;
            uint32_t dst = tb + r * 128 + (((cch ^ (r & 7))) << 4);
            cp16(dst, src + (size_t)(row0 + r) * ld + k0 + cch * 8);
        }
    }
}

__global__ __launch_bounds__(256, 2) void mma_gemm(GemmJob j0, GemmJob j1)
{
    const GemmJob j = (blockIdx.z == 0) ? j0 : j1;
    if ((int)blockIdx.x >= j.bx) return;

    extern __shared__ char smem[];
    const uint32_t sb = smem_u32(smem);
    const int tid = threadIdx.x;
    const int wid = tid >> 5;
    const int lane = tid & 31;
    const int warp_m = wid & 3;
    const int warp_n = wid >> 2;
    const int rowBase = blockIdx.y * 128;
    const int colBase = blockIdx.x * 128;

    float c[2][8][4];
#pragma unroll
    for (int i = 0; i < 2; ++i)
#pragma unroll
        for (int jn = 0; jn < 8; ++jn)
#pragma unroll
            for (int k = 0; k < 4; ++k) c[i][jn][k] = 0.f;

    const int NC1 = j.K1 / KC;
    const int NC2 = j.K2 / KC;
    const int NC = NC1 + NC2;

    issue_chunk(sb, j.A1, j.B1, j.K1, j.K1, rowBase, colBase, 0, tid);
    cp_commit();

#pragma unroll 1
    for (int ch = 0; ch < NC; ++ch) {
        const uint32_t cur = sb + (uint32_t)(ch & 1) * STAGE_B;
        if (ch + 1 < NC) {
            int nc = ch + 1;
            if (nc < NC1)
                issue_chunk(sb + (uint32_t)(nc & 1) * STAGE_B, j.A1, j.B1,
                            j.K1, j.K1, rowBase, colBase, nc * KC, tid);
            else
                issue_chunk(sb + (uint32_t)(nc & 1) * STAGE_B, j.A2, j.B2,
                            j.K2, j.K2, rowBase, colBase, (nc - NC1) * KC, tid);
            cp_commit();
            asm volatile("cp.async.wait_group 1;" ::: "memory");
        } else {
            cp_wait_all();
        }
        __syncthreads();

#pragma unroll
        for (int ks = 0; ks < 4; ++ks) {
            uint32_t ah[2][4], bh[4][4];
#pragma unroll
            for (int mf = 0; mf < 2; ++mf) {
                int row = warp_m * 32 + mf * 16 + ((lane >> 3) & 1) * 8 + (lane & 7);
                int chunk = ks * 2 + (lane >> 4);
                uint32_t ad = cur + row * 128 + ((chunk ^ (row & 7)) << 4);
                ldmx4(ah[mf], ad);
            }
#pragma unroll
            for (int nf2 = 0; nf2 < 4; ++nf2) {
                int row = warp_n * 64 + nf2 * 16 + (lane >> 4) * 8 + (lane & 7);
                int chunk = ks * 2 + ((lane >> 3) & 1);
                uint32_t bd = cur + TILE_B + row * 128 + ((chunk ^ (row & 7)) << 4);
                ldmx4(bh[nf2], bd);
            }
#pragma unroll
            for (int mf = 0; mf < 2; ++mf)
#pragma unroll
                for (int nf = 0; nf < 8; ++nf)
                    mma_f16(c[mf][nf], ah[mf], &bh[nf >> 1][(nf & 1) * 2]);
        }
        __syncthreads();
    }

    const int r0 = rowBase + warp_m * 32 + (lane >> 2);
    const int colb = colBase + warp_n * 64 + (lane & 3) * 2;
#pragma unroll
    for (int mf = 0; mf < 2; ++mf) {
        int row = r0 + mf * 16;
#pragma unroll
        for (int nf = 0; nf < 8; ++nf) {
            int col = colb + nf * 8;
            if (col < j.Nvalid) {
                float b0 = 0.f, b1 = 0.f;
                if (j.bias) { b0 = j.bias[col]; b1 = j.bias[col + 1]; }
                float2 v0, v1;
                v0.x = c[mf][nf][0] + b0; v0.y = c[mf][nf][1] + b1;
                v1.x = c[mf][nf][2] + b0; v1.y = c[mf][nf][3] + b1;
                if (j.do_relu) {
                    v0.x = fmaxf(v0.x, 0.f); v0.y = fmaxf(v0.y, 0.f);
                    v1.x = fmaxf(v1.x, 0.f); v1.y = fmaxf(v1.y, 0.f);
                }
                if (j.Ch) {
                    __half2 h0 = __floats2half2_rn(v0.x, v0.y);
                    __half2 h1 = __floats2half2_rn(v1.x, v1.y);
                    *(__half2*)(j.Ch + (size_t)row * j.ldc + col) = h0;
                    *(__half2*)(j.Ch + (size_t)(row + 8) * j.ldc + col) = h1;
                } else {
                    *(float2*)(j.C + (size_t)row * j.ldc + col) = v0;
                    *(float2*)(j.C + (size_t)(row + 8) * j.ldc + col) = v1;
                }
            }
        }
    }
}

// ================= conversion kernels (merged; also zeroes g_cnt) =================
__global__ void round_rows2(const float* __restrict__ a, __half* __restrict__ ah,
                            const float* __restrict__ b, __half* __restrict__ bh) {
    const size_t T1 = (size_t)N_NODES * 1024;
    const size_t T2 = (size_t)N_NODES * 320;
    size_t gid = (size_t)blockIdx.x * blockDim.x + threadIdx.x;
    size_t stride = (size_t)gridDim.x * blockDim.x;
    for (size_t i = gid; i < (size_t)N_NODES; i += stride) g_cnt[i] = 0;
    for (size_t i = gid; i < T1 + T2; i += stride) {
        if (i < T1) {
            ah[i] = __float2half_rn(a[i]);
        } else {
            size_t jj = i - T1;
            int row = (int)(jj / 320);
            int col = (int)(jj % 320);
            float v = (col < 300) ? b[(size_t)row * 300 + col] : 0.f;
            bh[jj] = __float2half_rn(v);
        }
    }
}

__global__ void transpose_round2(const float* __restrict__ W0, const float* __restrict__ W1,
                                 int ldw, int K, int N,
                                 __half* __restrict__ hi, int Kd, int n0_0, int n0_1) {
    const float* W = blockIdx.z ? W1 : W0;
    const int n0 = blockIdx.z ? n0_1 : n0_0;
    __shared__ float tile[32][33];
    int kb = blockIdx.y * 32, nb = blockIdx.x * 32;
#pragma unroll
    for (int i = 0; i < 4; ++i) {
        int k = kb + threadIdx.y + i * 8;
        int n = nb + threadIdx.x;
        tile[threadIdx.y + i * 8][threadIdx.x] = (k < K && n < N) ? W[(size_t)k * ldw + n] : 0.f;
    }
    __syncthreads();
#pragma unroll
    for (int i = 0; i < 4; ++i) {
        int n = nb + threadIdx.y + i * 8;
        int k = kb + threadIdx.x;
        if (n < N && k < Kd)
            hi[(size_t)(n0 + n) * Kd + k] = __float2half_rn(tile[threadIdx.x][threadIdx.y + i * 8]);
    }
}

// ================= CSR construction =================
__global__ void hist_kernel(const int* __restrict__ dst) {
    int e = blockIdx.x * blockDim.x + threadIdx.x;
    if (e < N_EDGES) atomicAdd(&g_cnt[dst[e]], 1);
}
__global__ __launch_bounds__(1024) void scan_kernel() {
    __shared__ int sm[1024];
    int t = threadIdx.x;
    int loc[8];
    int s = 0;
#pragma unroll
    for (int i = 0; i < 8; ++i) { loc[i] = g_cnt[t * 8 + i]; s += loc[i]; }
    sm[t] = s;
    __syncthreads();
    for (int off = 1; off < 1024; off <<= 1) {
        int v = sm[t];
        if (t >= off) v += sm[t - off];
        __syncthreads();
        sm[t] = v;
        __syncthreads();
    }
    int run = (t == 0) ? 0 : sm[t - 1];
#pragma unroll
    for (int i = 0; i < 8; ++i) {
        g_off[t * 8 + i] = run;
        g_fill[t * 8 + i] = run;
        run += loc[i];
    }
}
__global__ void fill_kernel(const int* __restrict__ dst) {
    int e = blockIdx.x * blockDim.x + threadIdx.x;
    if (e < N_EDGES) {
        int pos = atomicAdd(&g_fill[dst[e]], 1);
        g_eid[pos] = e;
    }
}

// ================= merged score+softmax+combine kernel (R13 version) =================
#define COMB_SMEM ((2 * CACHE_E * 1024 + CACHE_E * 320) * 2)

__global__ __launch_bounds__(256) void combine_all(
    const float* __restrict__ n_f, const float* __restrict__ w2v,
    const float* __restrict__ s_f, const int* __restrict__ src,
    const float* __restrict__ We, const float* __restrict__ be,
    const float* __restrict__ Wa,
    const float* __restrict__ bel, const float* __restrict__ Wal)
{
    extern __shared__ __half dyn[];
    __half* efc = dyn;
    __half* nfc = dyn + CACHE_E * 1024;
    __half* wvc = dyn + 2 * CACHE_E * 1024;
    const uint32_t efc_b = smem_u32(efc);
    const uint32_t nfc_b = smem_u32(nfc);
    const uint32_t wvc_b = smem_u32(wvc);

    const int d = blockIdx.x;
    const int t = threadIdx.x;
    const int lane = t & 31;
    const int deg = g_cnt[d];
    const int start = g_off[d];
    const int cdeg = (deg < CACHE_E) ? deg : CACHE_E;

    __shared__ int sm_eid[MAXDEG], sm_src[MAXDEG];
    __shared__ float sm_af[MAXDEG], sm_afl[MAXDEG];
    __shared__ float sm_scal[4];

    for (int i = t; i < deg; i += 256) {
        int e = g_eid[start + i];
        sm_eid[i] = e;
        sm_src[i] = src[e];
    }
    for (int i = t; i < MAXDEG; i += 256) { sm_af[i] = 0.f; sm_afl[i] = 0.f; }
    __syncthreads();

    // ---------- Phase A0: bulk-gather P rows (full MLP) ----------
#pragma unroll 1
    for (int i = 0; i < cdeg; ++i)
        cp8(efc_b + (uint32_t)(i * 1024 + 4 * t) * 2,
            g_P_h + (size_t)sm_src[i] * 2048 + 4 * t);
    cp_commit();

    const float4* Ws4 = (const float4*)(We + (size_t)1024 * 1024);
    float4 wsr[16];
#pragma unroll
    for (int k = 0; k < 16; ++k) wsr[k] = Ws4[k * 256 + t];

    float4 p3r;
    {
        uint2 pr = *(const uint2*)(g_P_h + (size_t)d * 2048 + 1024 + 4 * t);
        p3r = h4_to_f4(pr);
        float4 ber = ((const float4*)be)[t];
        p3r.x += ber.x; p3r.y += ber.y; p3r.z += ber.z; p3r.w += ber.w;
    }
    float4 war = ((const float4*)Wa)[t];
    float4 q2r = make_float4(0.f, 0.f, 0.f, 0.f);
    float4 walr = make_float4(0.f, 0.f, 0.f, 0.f);
    if (t < 150) {
        uint2 qr = *(const uint2*)(g_Q_h + (size_t)d * 1200 + 600 + 4 * t);
        q2r = h4_to_f4(qr);
        float4 belr = ((const float4*)bel)[t];
        q2r.x += belr.x; q2r.y += belr.y; q2r.z += belr.z; q2r.w += belr.w;
        walr = ((const float4*)Wal)[t];
    }

    cp_wait_all();
    __syncthreads();

    // ---------- Phase A: e_f + scores ----------
    uint2 qr_c = make_uint2(0u, 0u);
    if (deg > 0 && t < 150)
        qr_c = *(const uint2*)(g_Q_h + (size_t)sm_src[0] * 1200 + 4 * t);

#pragma unroll 1
    for (int i = 0; i < deg; ++i) {
        const int eid = sm_eid[i];

        const float4* sf4 = (const float4*)(s_f + (size_t)eid * 16);
        float4 sv0 = __ldg(sf4 + 0), sv1 = __ldg(sf4 + 1);
        float4 sv2 = __ldg(sf4 + 2), sv3 = __ldg(sf4 + 3);

        uint2 qr_n = make_uint2(0u, 0u);
        if (i + 1 < deg && t < 150)
            qr_n = *(const uint2*)(g_Q_h + (size_t)sm_src[i + 1] * 1200 + 4 * t);

        uint2 pr;
        if (i < CACHE_E)
            pr = *(const uint2*)(efc + i * 1024 + 4 * t);
        else
            pr = *(const uint2*)(g_P_h + (size_t)sm_src[i] * 2048 + 4 * t);

        float4 v = h4_to_f4(pr);
        v.x += p3r.x; v.y += p3r.y; v.z += p3r.z; v.w += p3r.w;
        float sfs[16] = {sv0.x, sv0.y, sv0.z, sv0.w, sv1.x, sv1.y, sv1.z, sv1.w,
                         sv2.x, sv2.y, sv2.z, sv2.w, sv3.x, sv3.y, sv3.z, sv3.w};
#pragma unroll
        for (int k = 0; k < 16; ++k) {
            v.x = fmaf(sfs[k], wsr[k].x, v.x); v.y = fmaf(sfs[k], wsr[k].y, v.y);
            v.z = fmaf(sfs[k], wsr[k].z, v.z); v.w = fmaf(sfs[k], wsr[k].w, v.w);
        }
        v.x = fmaxf(v.x, 0.f); v.y = fmaxf(v.y, 0.f);
        v.z = fmaxf(v.z, 0.f); v.w = fmaxf(v.w, 0.f);
        if (i < CACHE_E) {
            __half2 h0 = __floats2half2_rn(v.x, v.y);
            __half2 h1 = __floats2half2_rn(v.z, v.w);
            uint2 pk;
            pk.x = *(uint32_t*)&h0;
            pk.y = *(uint32_t*)&h1;
            *(uint2*)(efc + i * 1024 + 4 * t) = pk;   // overwrite P row with e_f
        }

        float acc = v.x * war.x + v.y * war.y + v.z * war.z + v.w * war.w;

        float accl = 0.f;
        if (t < 150) {
            float4 u = h4_to_f4(qr_c);
            u.x += q2r.x; u.y += q2r.y; u.z += q2r.z; u.w += q2r.w;
            u.x = fmaxf(u.x, 0.f); u.y = fmaxf(u.y, 0.f);
            u.z = fmaxf(u.z, 0.f); u.w = fmaxf(u.w, 0.f);
            accl = u.x * walr.x + u.y * walr.y + u.z * walr.z + u.w * walr.w;
        }

#pragma unroll
        for (int off = 16; off > 0; off >>= 1) {
            acc += __shfl_down_sync(0xffffffffu, acc, off);
            accl += __shfl_down_sync(0xffffffffu, accl, off);
        }
        if (lane == 0) {
            atomicAdd(&sm_af[i], acc);
            if (accl != 0.f) atomicAdd(&sm_afl[i], accl);
        }
        qr_c = qr_n;
    }

    // ---------- Phase B0: bulk-gather nf / w2v rows (overlaps softmax) ----------
#pragma unroll 1
    for (int i = 0; i < cdeg; ++i) {
        int s = sm_src[i];
        cp8(nfc_b + (uint32_t)(i * 1024 + 4 * t) * 2,
            g_nf_h + (size_t)s * 1024 + 4 * t);
        if (t < 75)
            cp8(wvc_b + (uint32_t)(i * 320 + 4 * t) * 2,
                g_w2v_h + (size_t)s * 320 + 4 * t);
    }
    cp_commit();
    __syncthreads();

    // ---------- softmax scalars (warp 0) ----------
    if (t < 32) {
        float m = -1e30f, ml = -1e30f;
        for (int i = t; i < deg; i += 32) {
            m = fmaxf(m, sm_af[i]);
            ml = fmaxf(ml, sm_afl[i]);
        }
#pragma unroll
        for (int off = 16; off > 0; off >>= 1) {
            m = fmaxf(m, __shfl_xor_sync(0xffffffffu, m, off));
            ml = fmaxf(ml, __shfl_xor_sync(0xffffffffu, ml, off));
        }
        float den = 0.f, denl = 0.f;
        for (int i = t; i < deg; i += 32) {
            den += expf(sm_af[i] - m);
            denl += expf(sm_afl[i] - ml);
        }
#pragma unroll
        for (int off = 16; off > 0; off >>= 1) {
            den += __shfl_xor_sync(0xffffffffu, den, off);
            denl += __shfl_xor_sync(0xffffffffu, denl, off);
        }
        if (t == 0) {
            sm_scal[0] = m;
            sm_scal[1] = (deg > 0) ? 1.f / den : 0.f;
            sm_scal[2] = ml;
            sm_scal[3] = (deg > 0) ? 1.f / denl : 0.f;
        }
    }
    __syncthreads();

    {
        const float m = sm_scal[0], rden = sm_scal[1];
        const float ml = sm_scal[2], rdenl = sm_scal[3];
        for (int i = t; i < deg; i += 256) {
            sm_af[i] = expf(sm_af[i] - m) * rden;
            sm_afl[i] = expf(sm_afl[i] - ml) * rdenl;
        }
    }
    cp_wait_all();
    __syncthreads();

    // ---------- Phase B: weighted accumulate (smem-resident) ----------
    float4 acc = make_float4(0.f, 0.f, 0.f, 0.f);
    float4 accl = make_float4(0.f, 0.f, 0.f, 0.f);

#pragma unroll 1
    for (int i = 0; i < deg; ++i) {
        const float alpha = sm_af[i];
        const float alphal = sm_afl[i];

        float4 v, n;
        if (i < CACHE_E) {
            v = h4_to_f4(*(const uint2*)(efc + i * 1024 + 4 * t));
            n = h4_to_f4(*(const uint2*)(nfc + i * 1024 + 4 * t));
        } else {
            const int s = sm_src[i];
            const int eid = sm_eid[i];
            uint2 pr = *(const uint2*)(g_P_h + (size_t)s * 2048 + 4 * t);
            v = h4_to_f4(pr);
            v.x += p3r.x; v.y += p3r.y; v.z += p3r.z; v.w += p3r.w;
            const float4* sf4 = (const float4*)(s_f + (size_t)eid * 16);
            float4 sv0 = __ldg(sf4 + 0), sv1 = __ldg(sf4 + 1);
            float4 sv2 = __ldg(sf4 + 2), sv3 = __ldg(sf4 + 3);
            float sfs[16] = {sv0.x, sv0.y, sv0.z, sv0.w, sv1.x, sv1.y, sv1.z, sv1.w,
                             sv2.x, sv2.y, sv2.z, sv2.w, sv3.x, sv3.y, sv3.z, sv3.w};
#pragma unroll
            for (int k = 0; k < 16; ++k) {
                v.x = fmaf(sfs[k], wsr[k].x, v.x); v.y = fmaf(sfs[k], wsr[k].y, v.y);
                v.z = fmaf(sfs[k], wsr[k].z, v.z); v.w = fmaf(sfs[k], wsr[k].w, v.w);
            }
            v.x = fmaxf(v.x, 0.f); v.y = fmaxf(v.y, 0.f);
            v.z = fmaxf(v.z, 0.f); v.w = fmaxf(v.w, 0.f);
            n = h4_to_f4(*(const uint2*)(g_nf_h + (size_t)s * 1024 + 4 * t));
        }

        acc.x = fmaf(alpha, n.x + v.x, acc.x);
        acc.y = fmaf(alpha, n.y + v.y, acc.y);
        acc.z = fmaf(alpha, n.z + v.z, acc.z);
        acc.w = fmaf(alpha, n.w + v.w, acc.w);

        if (t < 75) {
            float4 w;
            if (i < CACHE_E)
                w = h4_to_f4(*(const uint2*)(wvc + i * 320 + 4 * t));
            else
                w = h4_to_f4(*(const uint2*)(g_w2v_h + (size_t)sm_src[i] * 320 + 4 * t));
            accl.x = fmaf(alphal, w.x, accl.x);
            accl.y = fmaf(alphal, w.y, accl.y);
            accl.z = fmaf(alphal, w.z, accl.z);
            accl.w = fmaf(alphal, w.w, accl.w);
        }
    }

    // ---------- write fp16 ----------
    {
        size_t o = (size_t)d * 1024 + 4 * t;
        g_zf_h[o + 0] = __float2half_rn(acc.x);
        g_zf_h[o + 1] = __float2half_rn(acc.y);
        g_zf_h[o + 2] = __float2half_rn(acc.z);
        g_zf_h[o + 3] = __float2half_rn(acc.w);
    }
    if (t < 75) {
        size_t o = (size_t)d * 320 + 4 * t;
        g_zfl_h[o + 0] = __float2half_rn(accl.x);
        g_zfl_h[o + 1] = __float2half_rn(accl.y);
        g_zfl_h[o + 2] = __float2half_rn(accl.z);
        g_zfl_h[o + 3] = __float2half_rn(accl.w);
    }
}

// ================= launch =================
extern "C" void kernel_launch(void* const* d_in, const int* in_sizes, int n_in,
                              void* d_out, int out_size) {
    const float* n_f  = (const float*)d_in[0];
    const float* w2v  = (const float*)d_in[1];
    const float* s_f  = (const float*)d_in[2];
    const int*   src  = (const int*)d_in[3];
    const int*   dst  = (const int*)d_in[4];
    const float* We   = (const float*)d_in[5];
    const float* be   = (const float*)d_in[6];
    const float* Wel  = (const float*)d_in[7];
    const float* bel  = (const float*)d_in[8];
    const float* Wa   = (const float*)d_in[9];
    const float* Wal  = (const float*)d_in[11];
    const float* Wn   = (const float*)d_in[13];
    const float* bn   = (const float*)d_in[14];
    const float* Wnl  = (const float*)d_in[15];
    const float* bnl  = (const float*)d_in[16];

    float* out      = (float*)d_out;
    float* out_lang = out + (size_t)N_NODES * 1024;

    __half *P_h, *Q_h;
    __half *nf_h, *w2v_h, *zf_h, *zfl_h;
    __half *WeT_h, *WnT_h, *WelT_h, *WnlT_h;
    cudaGetSymbolAddress((void**)&P_h, g_P_h);
    cudaGetSymbolAddress((void**)&Q_h, g_Q_h);
    cudaGetSymbolAddress((void**)&nf_h, g_nf_h);
    cudaGetSymbolAddress((void**)&w2v_h, g_w2v_h);
    cudaGetSymbolAddress((void**)&zf_h, g_zf_h);
    cudaGetSymbolAddress((void**)&zfl_h, g_zfl_h);
    cudaGetSymbolAddress((void**)&WeT_h, g_WeT_h);
    cudaGetSymbolAddress((void**)&WnT_h, g_WnT_h);
    cudaGetSymbolAddress((void**)&WelT_h, g_WelT_h);
    cudaGetSymbolAddress((void**)&WnlT_h, g_WnlT_h);

    cudaFuncSetAttribute(mma_gemm, cudaFuncAttributeMaxDynamicSharedMemorySize, GEMM_SMEM);
    cudaFuncSetAttribute(combine_all, cudaFuncAttributeMaxDynamicSharedMemorySize, COMB_SMEM);

    dim3 tblk(32, 8);

    round_rows2<<<2048, 256>>>(n_f, nf_h, w2v, w2v_h);   // also zeroes g_cnt
    transpose_round2<<<dim3(32, 32, 2), tblk>>>(We, We + (size_t)1040 * 1024,
                                                1024, 1024, 1024, WeT_h, 1024, 0, 1024);
    transpose_round2<<<dim3(19, 10, 2), tblk>>>(Wel, Wel + (size_t)300 * 600,
                                                600, 300, 600, WelT_h, 320, 0, 600);
    hist_kernel<<<64, 1024>>>(dst);
    scan_kernel<<<1, 1024>>>();
    fill_kernel<<<64, 1024>>>(dst);

    // batched projections: z=0 -> P, z=1 -> Q
    {
        GemmJob jp = {nullptr, P_h, 2048, 2048, nf_h, WeT_h, 1024,
                      nullptr, nullptr, 0, nullptr, 0, 16};
        GemmJob jq = {nullptr, Q_h, 1200, 1200, w2v_h, WelT_h, 320,
                      nullptr, nullptr, 0, nullptr, 0, 10};
        mma_gemm<<<dim3(16, 64, 2), 256, GEMM_SMEM>>>(jp, jq);
    }

    transpose_round2<<<dim3(32, 32, 2), tblk>>>(Wn, Wn + (size_t)1024 * 1024,
                                                1024, 1024, 1024, WnT_h, 1024, 0, 1024);
    transpose_round2<<<dim3(10, 10, 2), tblk>>>(Wnl, Wnl + (size_t)300 * 300,
                                                300, 300, 300, WnlT_h, 320, 0, 300);

    combine_all<<<N_NODES, 256, COMB_SMEM>>>(
        n_f, w2v, s_f, src, We, be, Wa, bel, Wal);

    // batched node-apply: z=0 -> out, z=1 -> out_lang
    {
        GemmJob jo = {out, nullptr, 1024, 1024, nf_h, WnT_h, 1024,
                      zf_h, WnT_h + (size_t)1024 * 1024, 1024, bn, 1, 8};
        GemmJob jl = {out_lang, nullptr, 300, 300, w2v_h, WnlT_h, 320,
                      zfl_h, WnlT_h + (size_t)300 * 320, 320, bnl, 1, 3};
        mma_gemm<<<dim3(8, 64, 2), 256, GEMM_SMEM>>>(jo, jl);
    }
}

// round 16
// speedup vs baseline: 1.1706x; 1.1146x over previous
#include <cuda_runtime.h>
#include <cuda_fp16.h>
#include <cstdint>
#include <cstddef>

#define N_NODES 8192
#define N_EDGES 65536
#define CACHE_E 12
#define MAXDEG 256

// ================= scratch (device globals) =================
__device__ __half g_P_h[(size_t)N_NODES * 2048];   // [P1 | P3]
__device__ __half g_Q_h[(size_t)N_NODES * 1200];   // [Q1 | Q2]
__device__ __half g_S_h[(size_t)N_EDGES * 1024];   // s_f @ Ws  (128 MB)
__device__ __half g_sfp_h[(size_t)N_EDGES * 64];   // s_f padded fp16
__device__ __half g_WsT_h[(size_t)1024 * 64];      // Ws^T padded

// CSR by dst
__device__ int g_cnt[N_NODES];
__device__ int g_off[N_NODES];
__device__ int g_fill[N_NODES];
__device__ int g_eid[N_EDGES];

// fp16 operands
__device__ __half g_nf_h[(size_t)N_NODES * 1024];
__device__ __half g_w2v_h[(size_t)N_NODES * 320];
__device__ __half g_zf_h[(size_t)N_NODES * 1024];
__device__ __half g_zfl_h[(size_t)N_NODES * 320];
__device__ __half g_WeT_h[(size_t)2048 * 1024];
__device__ __half g_WnT_h[(size_t)2048 * 1024];
__device__ __half g_WelT_h[(size_t)1280 * 320];
__device__ __half g_WnlT_h[(size_t)768 * 320];

// ================= small helpers =================
__device__ __forceinline__ uint32_t smem_u32(const void* p) {
    uint32_t a;
    asm("{ .reg .u64 t; cvta.to.shared.u64 t, %1; cvt.u32.u64 %0, t; }" : "=r"(a) : "l"(p));
    return a;
}
__device__ __forceinline__ void cp16(uint32_t dst, const void* src) {
    asm volatile("cp.async.cg.shared.global [%0], [%1], 16;" :: "r"(dst), "l"(src) : "memory");
}
__device__ __forceinline__ void cp8(uint32_t dst, const void* src) {
    asm volatile("cp.async.ca.shared.global [%0], [%1], 8;" :: "r"(dst), "l"(src) : "memory");
}
__device__ __forceinline__ void cp_commit() {
    asm volatile("cp.async.commit_group;" ::: "memory");
}
__device__ __forceinline__ void cp_wait_all() {
    asm volatile("cp.async.wait_group 0;" ::: "memory");
}
__device__ __forceinline__ void ldmx4(uint32_t* r, uint32_t addr) {
    asm volatile("ldmatrix.sync.aligned.m8n8.x4.shared.b16 {%0,%1,%2,%3}, [%4];"
                 : "=r"(r[0]), "=r"(r[1]), "=r"(r[2]), "=r"(r[3]) : "r"(addr));
}
__device__ __forceinline__ void mma_f16(float* c, const uint32_t* a, const uint32_t* b) {
    asm volatile(
        "mma.sync.aligned.m16n8k16.row.col.f32.f16.f16.f32 "
        "{%0,%1,%2,%3}, {%4,%5,%6,%7}, {%8,%9}, {%0,%1,%2,%3};"
        : "+f"(c[0]), "+f"(c[1]), "+f"(c[2]), "+f"(c[3])
        : "r"(a[0]), "r"(a[1]), "r"(a[2]), "r"(a[3]), "r"(b[0]), "r"(b[1]));
}
__device__ __forceinline__ float4 h4_to_f4(uint2 pk) {
    __half2 h0 = *(__half2*)&pk.x;
    __half2 h1 = *(__half2*)&pk.y;
    float2 f0 = __half22float2(h0);
    float2 f1 = __half22float2(h1);
    return make_float4(f0.x, f0.y, f1.x, f1.y);
}

// ================= batched fp16 HMMA GEMM (unchanged, known-good) =================
#define KC 64
#define TILE_B 16384
#define STAGE_B (2 * TILE_B)
#define GEMM_SMEM (2 * STAGE_B)

struct GemmJob {
    float* C; __half* Ch; int ldc; int Nvalid;
    const __half* A1; const __half* B1; int K1;
    const __half* A2; const __half* B2; int K2;
    const float* bias; int do_relu; int bx;
};

__device__ __forceinline__ void issue_chunk(
    uint32_t sb_stage,
    const __half* A, const __half* B,
    int ldA, int ldB, int rowBase, int colBase, int k0, int tid)
{
#pragma unroll
    for (int t = 0; t < 2; ++t) {
        const __half* src = (t == 0) ? A : B;
        const int row0 = (t == 0) ? rowBase : colBase;
        const int ld = (t == 0) ? ldA : ldB;
        const uint32_t tb = sb_stage + t * TILE_B;
#pragma unroll
        for (int i = 0; i < 4; ++i) {
            int idx = i * 256 + tid;
            int r = idx >> 3;
            int cch = idx & 7;
            uint32_t dst = tb + r * 128 + (((cch ^ (r & 7))) << 4);
            cp16(dst, src + (size_t)(row0 + r) * ld + k0 + cch * 8);
        }
    }
}

__global__ __launch_bounds__(256, 2) void mma_gemm(GemmJob j0, GemmJob j1)
{
    const GemmJob j = (blockIdx.z == 0) ? j0 : j1;
    if ((int)blockIdx.x >= j.bx) return;

    extern __shared__ char smem[];
    const uint32_t sb = smem_u32(smem);
    const int tid = threadIdx.x;
    const int wid = tid >> 5;
    const int lane = tid & 31;
    const int warp_m = wid & 3;
    const int warp_n = wid >> 2;
    const int rowBase = blockIdx.y * 128;
    const int colBase = blockIdx.x * 128;

    float c[2][8][4];
#pragma unroll
    for (int i = 0; i < 2; ++i)
#pragma unroll
        for (int jn = 0; jn < 8; ++jn)
#pragma unroll
            for (int k = 0; k < 4; ++k) c[i][jn][k] = 0.f;

    const int NC1 = j.K1 / KC;
    const int NC2 = j.K2 / KC;
    const int NC = NC1 + NC2;

    issue_chunk(sb, j.A1, j.B1, j.K1, j.K1, rowBase, colBase, 0, tid);
    cp_commit();

#pragma unroll 1
    for (int ch = 0; ch < NC; ++ch) {
        const uint32_t cur = sb + (uint32_t)(ch & 1) * STAGE_B;
        if (ch + 1 < NC) {
            int nc = ch + 1;
            if (nc < NC1)
                issue_chunk(sb + (uint32_t)(nc & 1) * STAGE_B, j.A1, j.B1,
                            j.K1, j.K1, rowBase, colBase, nc * KC, tid);
            else
                issue_chunk(sb + (uint32_t)(nc & 1) * STAGE_B, j.A2, j.B2,
                            j.K2, j.K2, rowBase, colBase, (nc - NC1) * KC, tid);
            cp_commit();
            asm volatile("cp.async.wait_group 1;" ::: "memory");
        } else {
            cp_wait_all();
        }
        __syncthreads();

#pragma unroll
        for (int ks = 0; ks < 4; ++ks) {
            uint32_t ah[2][4], bh[4][4];
#pragma unroll
            for (int mf = 0; mf < 2; ++mf) {
                int row = warp_m * 32 + mf * 16 + ((lane >> 3) & 1) * 8 + (lane & 7);
                int chunk = ks * 2 + (lane >> 4);
                uint32_t ad = cur + row * 128 + ((chunk ^ (row & 7)) << 4);
                ldmx4(ah[mf], ad);
            }
#pragma unroll
            for (int nf2 = 0; nf2 < 4; ++nf2) {
                int row = warp_n * 64 + nf2 * 16 + (lane >> 4) * 8 + (lane & 7);
                int chunk = ks * 2 + ((lane >> 3) & 1);
                uint32_t bd = cur + TILE_B + row * 128 + ((chunk ^ (row & 7)) << 4);
                ldmx4(bh[nf2], bd);
            }
#pragma unroll
            for (int mf = 0; mf < 2; ++mf)
#pragma unroll
                for (int nf = 0; nf < 8; ++nf)
                    mma_f16(c[mf][nf], ah[mf], &bh[nf >> 1][(nf & 1) * 2]);
        }
        __syncthreads();
    }

    const int r0 = rowBase + warp_m * 32 + (lane >> 2);
    const int colb = colBase + warp_n * 64 + (lane & 3) * 2;
#pragma unroll
    for (int mf = 0; mf < 2; ++mf) {
        int row = r0 + mf * 16;
#pragma unroll
        for (int nf = 0; nf < 8; ++nf) {
            int col = colb + nf * 8;
            if (col < j.Nvalid) {
                float b0 = 0.f, b1 = 0.f;
                if (j.bias) { b0 = j.bias[col]; b1 = j.bias[col + 1]; }
                float2 v0, v1;
                v0.x = c[mf][nf][0] + b0; v0.y = c[mf][nf][1] + b1;
                v1.x = c[mf][nf][2] + b0; v1.y = c[mf][nf][3] + b1;
                if (j.do_relu) {
                    v0.x = fmaxf(v0.x, 0.f); v0.y = fmaxf(v0.y, 0.f);
                    v1.x = fmaxf(v1.x, 0.f); v1.y = fmaxf(v1.y, 0.f);
                }
                if (j.Ch) {
                    __half2 h0 = __floats2half2_rn(v0.x, v0.y);
                    __half2 h1 = __floats2half2_rn(v1.x, v1.y);
                    *(__half2*)(j.Ch + (size_t)row * j.ldc + col) = h0;
                    *(__half2*)(j.Ch + (size_t)(row + 8) * j.ldc + col) = h1;
                } else {
                    *(float2*)(j.C + (size_t)row * j.ldc + col) = v0;
                    *(float2*)(j.C + (size_t)(row + 8) * j.ldc + col) = v1;
                }
            }
        }
    }
}

// ================= conversion kernels (also zeroes g_cnt; also pads s_f) =================
__global__ void round_rows2(const float* __restrict__ a, __half* __restrict__ ah,
                            const float* __restrict__ b, __half* __restrict__ bh,
                            const float* __restrict__ sf, __half* __restrict__ sfp) {
    const size_t T1 = (size_t)N_NODES * 1024;
    const size_t T2 = (size_t)N_NODES * 320;
    const size_t T3 = (size_t)N_EDGES * 64;
    size_t gid = (size_t)blockIdx.x * blockDim.x + threadIdx.x;
    size_t stride = (size_t)gridDim.x * blockDim.x;
    for (size_t i = gid; i < (size_t)N_NODES; i += stride) g_cnt[i] = 0;
    for (size_t i = gid; i < T1 + T2 + T3; i += stride) {
        if (i < T1) {
            ah[i] = __float2half_rn(a[i]);
        } else if (i < T1 + T2) {
            size_t jj = i - T1;
            int row = (int)(jj / 320);
            int col = (int)(jj % 320);
            float v = (col < 300) ? b[(size_t)row * 300 + col] : 0.f;
            bh[jj] = __float2half_rn(v);
        } else {
            size_t jj = i - T1 - T2;
            int row = (int)(jj >> 6);
            int col = (int)(jj & 63);
            float v = (col < 16) ? sf[(size_t)row * 16 + col] : 0.f;
            sfp[jj] = __float2half_rn(v);
        }
    }
}

__global__ void transpose_round2(const float* __restrict__ W0, const float* __restrict__ W1,
                                 int ldw, int K, int N,
                                 __half* __restrict__ hi, int Kd, int n0_0, int n0_1) {
    const float* W = blockIdx.z ? W1 : W0;
    const int n0 = blockIdx.z ? n0_1 : n0_0;
    __shared__ float tile[32][33];
    int kb = blockIdx.y * 32, nb = blockIdx.x * 32;
#pragma unroll
    for (int i = 0; i < 4; ++i) {
        int k = kb + threadIdx.y + i * 8;
        int n = nb + threadIdx.x;
        tile[threadIdx.y + i * 8][threadIdx.x] = (k < K && n < N) ? W[(size_t)k * ldw + n] : 0.f;
    }
    __syncthreads();
#pragma unroll
    for (int i = 0; i < 4; ++i) {
        int n = nb + threadIdx.y + i * 8;
        int k = kb + threadIdx.x;
        if (n < N && k < Kd)
            hi[(size_t)(n0 + n) * Kd + k] = __float2half_rn(tile[threadIdx.x][threadIdx.y + i * 8]);
    }
}

// zero-fill WsT (padding cols 16..63 must be 0; transpose only writes k<16)
__global__ void zero_wst() {
    int i = blockIdx.x * blockDim.x + threadIdx.x;
    if (i < 1024 * 64) g_WsT_h[i] = __float2half_rn(0.f);
}

// ================= CSR construction =================
__global__ void hist_kernel(const int* __restrict__ dst) {
    int e = blockIdx.x * blockDim.x + threadIdx.x;
    if (e < N_EDGES) atomicAdd(&g_cnt[dst[e]], 1);
}
__global__ __launch_bounds__(1024) void scan_kernel() {
    __shared__ int sm[1024];
    int t = threadIdx.x;
    int loc[8];
    int s = 0;
#pragma unroll
    for (int i = 0; i < 8; ++i) { loc[i] = g_cnt[t * 8 + i]; s += loc[i]; }
    sm[t] = s;
    __syncthreads();
    for (int off = 1; off < 1024; off <<= 1) {
        int v = sm[t];
        if (t >= off) v += sm[t - off];
        __syncthreads();
        sm[t] = v;
        __syncthreads();
    }
    int run = (t == 0) ? 0 : sm[t - 1];
#pragma unroll
    for (int i = 0; i < 8; ++i) {
        g_off[t * 8 + i] = run;
        g_fill[t * 8 + i] = run;
        run += loc[i];
    }
}
__global__ void fill_kernel(const int* __restrict__ dst) {
    int e = blockIdx.x * blockDim.x + threadIdx.x;
    if (e < N_EDGES) {
        int pos = atomicAdd(&g_fill[dst[e]], 1);
        g_eid[pos] = e;
    }
}

// ================= merged score+softmax+combine kernel =================
#define COMB_SMEM ((2 * CACHE_E * 1024 + CACHE_E * 320) * 2)

__global__ __launch_bounds__(256, 3) void combine_all(
    const int* __restrict__ src,
    const float* __restrict__ be, const float* __restrict__ Wa,
    const float* __restrict__ bel, const float* __restrict__ Wal)
{
    extern __shared__ __half dyn[];
    __half* efc = dyn;                       // P rows -> e_f
    __half* nfc = dyn + CACHE_E * 1024;      // S rows -> nf rows
    __half* wvc = dyn + 2 * CACHE_E * 1024;
    const uint32_t efc_b = smem_u32(efc);
    const uint32_t nfc_b = smem_u32(nfc);
    const uint32_t wvc_b = smem_u32(wvc);

    const int d = blockIdx.x;
    const int t = threadIdx.x;
    const int lane = t & 31;
    const int deg = g_cnt[d];
    const int start = g_off[d];
    const int cdeg = (deg < CACHE_E) ? deg : CACHE_E;

    __shared__ int sm_eid[MAXDEG], sm_src[MAXDEG];
    __shared__ float sm_af[MAXDEG], sm_afl[MAXDEG];
    __shared__ float sm_scal[4];

    for (int i = t; i < deg; i += 256) {
        int e = g_eid[start + i];
        sm_eid[i] = e;
        sm_src[i] = src[e];
    }
    for (int i = t; i < MAXDEG; i += 256) { sm_af[i] = 0.f; sm_afl[i] = 0.f; }
    __syncthreads();

    // ---------- Phase A0: bulk-gather P1[src] rows and S[eid] rows ----------
#pragma unroll 1
    for (int i = 0; i < cdeg; ++i) {
        cp8(efc_b + (uint32_t)(i * 1024 + 4 * t) * 2,
            g_P_h + (size_t)sm_src[i] * 2048 + 4 * t);
        cp8(nfc_b + (uint32_t)(i * 1024 + 4 * t) * 2,
            g_S_h + (size_t)sm_eid[i] * 1024 + 4 * t);
    }
    cp_commit();

    float4 p3r;
    {
        uint2 pr = *(const uint2*)(g_P_h + (size_t)d * 2048 + 1024 + 4 * t);
        p3r = h4_to_f4(pr);
        float4 ber = ((const float4*)be)[t];
        p3r.x += ber.x; p3r.y += ber.y; p3r.z += ber.z; p3r.w += ber.w;
    }
    float4 war = ((const float4*)Wa)[t];
    float4 q2r = make_float4(0.f, 0.f, 0.f, 0.f);
    float4 walr = make_float4(0.f, 0.f, 0.f, 0.f);
    if (t < 150) {
        uint2 qr = *(const uint2*)(g_Q_h + (size_t)d * 1200 + 600 + 4 * t);
        q2r = h4_to_f4(qr);
        float4 belr = ((const float4*)bel)[t];
        q2r.x += belr.x; q2r.y += belr.y; q2r.z += belr.z; q2r.w += belr.w;
        walr = ((const float4*)Wal)[t];
    }

    cp_wait_all();
    __syncthreads();

    // ---------- Phase A: e_f + scores ----------
    uint2 qr_c = make_uint2(0u, 0u);
    if (deg > 0 && t < 150)
        qr_c = *(const uint2*)(g_Q_h + (size_t)sm_src[0] * 1200 + 4 * t);

#pragma unroll 1
    for (int i = 0; i < deg; ++i) {
        uint2 qr_n = make_uint2(0u, 0u);
        if (i + 1 < deg && t < 150)
            qr_n = *(const uint2*)(g_Q_h + (size_t)sm_src[i + 1] * 1200 + 4 * t);

        float4 v;
        if (i < CACHE_E) {
            float4 p = h4_to_f4(*(const uint2*)(efc + i * 1024 + 4 * t));
            float4 s = h4_to_f4(*(const uint2*)(nfc + i * 1024 + 4 * t));
            v.x = p.x + s.x + p3r.x; v.y = p.y + s.y + p3r.y;
            v.z = p.z + s.z + p3r.z; v.w = p.w + s.w + p3r.w;
        } else {
            float4 p = h4_to_f4(*(const uint2*)(g_P_h + (size_t)sm_src[i] * 2048 + 4 * t));
            float4 s = h4_to_f4(*(const uint2*)(g_S_h + (size_t)sm_eid[i] * 1024 + 4 * t));
            v.x = p.x + s.x + p3r.x; v.y = p.y + s.y + p3r.y;
            v.z = p.z + s.z + p3r.z; v.w = p.w + s.w + p3r.w;
        }
        v.x = fmaxf(v.x, 0.f); v.y = fmaxf(v.y, 0.f);
        v.z = fmaxf(v.z, 0.f); v.w = fmaxf(v.w, 0.f);
        if (i < CACHE_E) {
            __half2 h0 = __floats2half2_rn(v.x, v.y);
            __half2 h1 = __floats2half2_rn(v.z, v.w);
            uint2 pk;
            pk.x = *(uint32_t*)&h0;
            pk.y = *(uint32_t*)&h1;
            *(uint2*)(efc + i * 1024 + 4 * t) = pk;   // e_f replaces P row
        }

        float acc = v.x * war.x + v.y * war.y + v.z * war.z + v.w * war.w;

        float accl = 0.f;
        if (t < 150) {
            float4 u = h4_to_f4(qr_c);
            u.x = fmaxf(u.x + q2r.x, 0.f); u.y = fmaxf(u.y + q2r.y, 0.f);
            u.z = fmaxf(u.z + q2r.z, 0.f); u.w = fmaxf(u.w + q2r.w, 0.f);
            accl = u.x * walr.x + u.y * walr.y + u.z * walr.z + u.w * walr.w;
        }

#pragma unroll
        for (int off = 16; off > 0; off >>= 1) {
            acc += __shfl_down_sync(0xffffffffu, acc, off);
            accl += __shfl_down_sync(0xffffffffu, accl, off);
        }
        if (lane == 0) {
            atomicAdd(&sm_af[i], acc);
            if (accl != 0.f) atomicAdd(&sm_afl[i], accl);
        }
        qr_c = qr_n;
    }

    // ---------- Phase B0: bulk-gather nf / w2v rows (overlaps softmax) ----------
#pragma unroll 1
    for (int i = 0; i < cdeg; ++i) {
        int s = sm_src[i];
        cp8(nfc_b + (uint32_t)(i * 1024 + 4 * t) * 2,
            g_nf_h + (size_t)s * 1024 + 4 * t);
        if (t < 75)
            cp8(wvc_b + (uint32_t)(i * 320 + 4 * t) * 2,
                g_w2v_h + (size_t)s * 320 + 4 * t);
    }
    cp_commit();
    __syncthreads();

    // ---------- softmax scalars (warp 0) ----------
    if (t < 32) {
        float m = -1e30f, ml = -1e30f;
        for (int i = t; i < deg; i += 32) {
            m = fmaxf(m, sm_af[i]);
            ml = fmaxf(ml, sm_afl[i]);
        }
#pragma unroll
        for (int off = 16; off > 0; off >>= 1) {
            m = fmaxf(m, __shfl_xor_sync(0xffffffffu, m, off));
            ml = fmaxf(ml, __shfl_xor_sync(0xffffffffu, ml, off));
        }
        float den = 0.f, denl = 0.f;
        for (int i = t; i < deg; i += 32) {
            den += expf(sm_af[i] - m);
            denl += expf(sm_afl[i] - ml);
        }
#pragma unroll
        for (int off = 16; off > 0; off >>= 1) {
            den += __shfl_xor_sync(0xffffffffu, den, off);
            denl += __shfl_xor_sync(0xffffffffu, denl, off);
        }
        if (t == 0) {
            sm_scal[0] = m;
            sm_scal[1] = (deg > 0) ? 1.f / den : 0.f;
            sm_scal[2] = ml;
            sm_scal[3] = (deg > 0) ? 1.f / denl : 0.f;
        }
    }
    __syncthreads();

    {
        const float m = sm_scal[0], rden = sm_scal[1];
        const float ml = sm_scal[2], rdenl = sm_scal[3];
        for (int i = t; i < deg; i += 256) {
            sm_af[i] = expf(sm_af[i] - m) * rden;
            sm_afl[i] = expf(sm_afl[i] - ml) * rdenl;
        }
    }
    cp_wait_all();
    __syncthreads();

    // ---------- Phase B: weighted accumulate ----------
    float4 acc = make_float4(0.f, 0.f, 0.f, 0.f);
    float4 accl = make_float4(0.f, 0.f, 0.f, 0.f);

#pragma unroll 1
    for (int i = 0; i < deg; ++i) {
        const float alpha = sm_af[i];
        const float alphal = sm_afl[i];

        float4 v, n;
        if (i < CACHE_E) {
            v = h4_to_f4(*(const uint2*)(efc + i * 1024 + 4 * t));
            n = h4_to_f4(*(const uint2*)(nfc + i * 1024 + 4 * t));
        } else {
            const int s = sm_src[i];
            float4 p = h4_to_f4(*(const uint2*)(g_P_h + (size_t)s * 2048 + 4 * t));
            float4 sr = h4_to_f4(*(const uint2*)(g_S_h + (size_t)sm_eid[i] * 1024 + 4 * t));
            v.x = fmaxf(p.x + sr.x + p3r.x, 0.f);
            v.y = fmaxf(p.y + sr.y + p3r.y, 0.f);
            v.z = fmaxf(p.z + sr.z + p3r.z, 0.f);
            v.w = fmaxf(p.w + sr.w + p3r.w, 0.f);
            n = h4_to_f4(*(const uint2*)(g_nf_h + (size_t)s * 1024 + 4 * t));
        }

        acc.x = fmaf(alpha, n.x + v.x, acc.x);
        acc.y = fmaf(alpha, n.y + v.y, acc.y);
        acc.z = fmaf(alpha, n.z + v.z, acc.z);
        acc.w = fmaf(alpha, n.w + v.w, acc.w);

        if (t < 75) {
            float4 w;
            if (i < CACHE_E)
                w = h4_to_f4(*(const uint2*)(wvc + i * 320 + 4 * t));
            else
                w = h4_to_f4(*(const uint2*)(g_w2v_h + (size_t)sm_src[i] * 320 + 4 * t));
            accl.x = fmaf(alphal, w.x, accl.x);
            accl.y = fmaf(alphal, w.y, accl.y);
            accl.z = fmaf(alphal, w.z, accl.z);
            accl.w = fmaf(alphal, w.w, accl.w);
        }
    }

    // ---------- write fp16 ----------
    {
        size_t o = (size_t)d * 1024 + 4 * t;
        g_zf_h[o + 0] = __float2half_rn(acc.x);
        g_zf_h[o + 1] = __float2half_rn(acc.y);
        g_zf_h[o + 2] = __float2half_rn(acc.z);
        g_zf_h[o + 3] = __float2half_rn(acc.w);
    }
    if (t < 75) {
        size_t o = (size_t)d * 320 + 4 * t;
        g_zfl_h[o + 0] = __float2half_rn(accl.x);
        g_zfl_h[o + 1] = __float2half_rn(accl.y);
        g_zfl_h[o + 2] = __float2half_rn(accl.z);
        g_zfl_h[o + 3] = __float2half_rn(accl.w);
    }
}

// ================= launch =================
extern "C" void kernel_launch(void* const* d_in, const int* in_sizes, int n_in,
                              void* d_out, int out_size) {
    const float* n_f  = (const float*)d_in[0];
    const float* w2v  = (const float*)d_in[1];
    const float* s_f  = (const float*)d_in[2];
    const int*   src  = (const int*)d_in[3];
    const int*   dst  = (const int*)d_in[4];
    const float* We   = (const float*)d_in[5];
    const float* be   = (const float*)d_in[6];
    const float* Wel  = (const float*)d_in[7];
    const float* bel  = (const float*)d_in[8];
    const float* Wa   = (const float*)d_in[9];
    const float* Wal  = (const float*)d_in[11];
    const float* Wn   = (const float*)d_in[13];
    const float* bn   = (const float*)d_in[14];
    const float* Wnl  = (const float*)d_in[15];
    const float* bnl  = (const float*)d_in[16];

    float* out      = (float*)d_out;
    float* out_lang = out + (size_t)N_NODES * 1024;

    __half *P_h, *Q_h, *S_h, *sfp_h, *WsT_h;
    __half *nf_h, *w2v_h, *zf_h, *zfl_h;
    __half *WeT_h, *WnT_h, *WelT_h, *WnlT_h;
    cudaGetSymbolAddress((void**)&P_h, g_P_h);
    cudaGetSymbolAddress((void**)&Q_h, g_Q_h);
    cudaGetSymbolAddress((void**)&S_h, g_S_h);
    cudaGetSymbolAddress((void**)&sfp_h, g_sfp_h);
    cudaGetSymbolAddress((void**)&WsT_h, g_WsT_h);
    cudaGetSymbolAddress((void**)&nf_h, g_nf_h);
    cudaGetSymbolAddress((void**)&w2v_h, g_w2v_h);
    cudaGetSymbolAddress((void**)&zf_h, g_zf_h);
    cudaGetSymbolAddress((void**)&zfl_h, g_zfl_h);
    cudaGetSymbolAddress((void**)&WeT_h, g_WeT_h);
    cudaGetSymbolAddress((void**)&WnT_h, g_WnT_h);
    cudaGetSymbolAddress((void**)&WelT_h, g_WelT_h);
    cudaGetSymbolAddress((void**)&WnlT_h, g_WnlT_h);

    cudaFuncSetAttribute(mma_gemm, cudaFuncAttributeMaxDynamicSharedMemorySize, GEMM_SMEM);
    cudaFuncSetAttribute(combine_all, cudaFuncAttributeMaxDynamicSharedMemorySize, COMB_SMEM);

    dim3 tblk(32, 8);

    round_rows2<<<2048, 256>>>(n_f, nf_h, w2v, w2v_h, s_f, sfp_h);
    zero_wst<<<64, 1024>>>();
    transpose_round2<<<dim3(32, 32, 2), tblk>>>(We, We + (size_t)1040 * 1024,
                                                1024, 1024, 1024, WeT_h, 1024, 0, 1024);
    transpose_round2<<<dim3(32, 1, 1), tblk>>>(We + (size_t)1024 * 1024, nullptr,
                                               1024, 16, 1024, WsT_h, 64, 0, 0);
    transpose_round2<<<dim3(19, 10, 2), tblk>>>(Wel, Wel + (size_t)300 * 600,
                                                600, 300, 600, WelT_h, 320, 0, 600);
    hist_kernel<<<64, 1024>>>(dst);
    scan_kernel<<<1, 1024>>>();
    fill_kernel<<<64, 1024>>>(dst);

    // batched projections: z=0 -> P, z=1 -> Q
    {
        GemmJob jp = {nullptr, P_h, 2048, 2048, nf_h, WeT_h, 1024,
                      nullptr, nullptr, 0, nullptr, 0, 16};
        GemmJob jq = {nullptr, Q_h, 1200, 1200, w2v_h, WelT_h, 320,
                      nullptr, nullptr, 0, nullptr, 0, 10};
        mma_gemm<<<dim3(16, 64, 2), 256, GEMM_SMEM>>>(jp, jq);
    }

    // edge S GEMM: S[E,1024] = sfp[E,64] @ WsT^T
    {
        GemmJob js = {nullptr, S_h, 1024, 1024, sfp_h, WsT_h, 64,
                      nullptr, nullptr, 0, nullptr, 0, 8};
        mma_gemm<<<dim3(8, 512, 1), 256, GEMM_SMEM>>>(js, js);
    }

    transpose_round2<<<dim3(32, 32, 2), tblk>>>(Wn, Wn + (size_t)1024 * 1024,
                                                1024, 1024, 1024, WnT_h, 1024, 0, 1024);
    transpose_round2<<<dim3(10, 10, 2), tblk>>>(Wnl, Wnl + (size_t)300 * 300,
                                                300, 300, 300, WnlT_h, 320, 0, 300);

    combine_all<<<N_NODES, 256, COMB_SMEM>>>(src, be, Wa, bel, Wal);

    // batched node-apply: z=0 -> out, z=1 -> out_lang
    {
        GemmJob jo = {out, nullptr, 1024, 1024, nf_h, WnT_h, 1024,
                      zf_h, WnT_h + (size_t)1024 * 1024, 1024, bn, 1, 8};
        GemmJob jl = {out_lang, nullptr, 300, 300, w2v_h, WnlT_h, 320,
                      zfl_h, WnlT_h + (size_t)300 * 320, 320, bnl, 1, 3};
        mma_gemm<<<dim3(8, 64, 2), 256, GEMM_SMEM>>>(jo, jl);
    }
}

// round 17
// speedup vs baseline: 1.1718x; 1.0010x over previous
#include <cuda_runtime.h>
#include <cuda_fp16.h>
#include <cstdint>
#include <cstddef>

#define N_NODES 8192
#define N_EDGES 65536
#define CACHE_E 14
#define MAXDEG 256

// ================= scratch (device globals) =================
__device__ __half g_P_h[(size_t)N_NODES * 2048];   // [P1 | P3]
__device__ __half g_Q_h[(size_t)N_NODES * 1200];   // [Q1 | Q2]
__device__ __half g_S_h[(size_t)N_EDGES * 1024];   // s_f @ Ws  (128 MB)
__device__ __half g_sfp_h[(size_t)N_EDGES * 64];   // s_f padded fp16
__device__ __half g_WsT_h[(size_t)1024 * 64];      // Ws^T padded

// CSR by dst
__device__ int g_cnt[N_NODES];
__device__ int g_off[N_NODES];
__device__ int g_fill[N_NODES];
__device__ int g_eid[N_EDGES];

// fp16 operands
__device__ __half g_nf_h[(size_t)N_NODES * 1024];
__device__ __half g_w2v_h[(size_t)N_NODES * 320];
__device__ __half g_zf_h[(size_t)N_NODES * 1024];
__device__ __half g_zfl_h[(size_t)N_NODES * 320];
__device__ __half g_WeT_h[(size_t)2048 * 1024];
__device__ __half g_WnT_h[(size_t)2048 * 1024];
__device__ __half g_WelT_h[(size_t)1280 * 320];
__device__ __half g_WnlT_h[(size_t)768 * 320];

// ================= small helpers =================
__device__ __forceinline__ uint32_t smem_u32(const void* p) {
    uint32_t a;
    asm("{ .reg .u64 t; cvta.to.shared.u64 t, %1; cvt.u32.u64 %0, t; }" : "=r"(a) : "l"(p));
    return a;
}
__device__ __forceinline__ void cp16(uint32_t dst, const void* src) {
    asm volatile("cp.async.cg.shared.global [%0], [%1], 16;" :: "r"(dst), "l"(src) : "memory");
}
__device__ __forceinline__ void cp8(uint32_t dst, const void* src) {
    asm volatile("cp.async.ca.shared.global [%0], [%1], 8;" :: "r"(dst), "l"(src) : "memory");
}
__device__ __forceinline__ void cp_commit() {
    asm volatile("cp.async.commit_group;" ::: "memory");
}
__device__ __forceinline__ void cp_wait_all() {
    asm volatile("cp.async.wait_group 0;" ::: "memory");
}
__device__ __forceinline__ void ldmx4(uint32_t* r, uint32_t addr) {
    asm volatile("ldmatrix.sync.aligned.m8n8.x4.shared.b16 {%0,%1,%2,%3}, [%4];"
                 : "=r"(r[0]), "=r"(r[1]), "=r"(r[2]), "=r"(r[3]) : "r"(addr));
}
__device__ __forceinline__ void mma_f16(float* c, const uint32_t* a, const uint32_t* b) {
    asm volatile(
        "mma.sync.aligned.m16n8k16.row.col.f32.f16.f16.f32 "
        "{%0,%1,%2,%3}, {%4,%5,%6,%7}, {%8,%9}, {%0,%1,%2,%3};"
        : "+f"(c[0]), "+f"(c[1]), "+f"(c[2]), "+f"(c[3])
        : "r"(a[0]), "r"(a[1]), "r"(a[2]), "r"(a[3]), "r"(b[0]), "r"(b[1]));
}
__device__ __forceinline__ float4 h4_to_f4(uint2 pk) {
    __half2 h0 = *(__half2*)&pk.x;
    __half2 h1 = *(__half2*)&pk.y;
    float2 f0 = __half22float2(h0);
    float2 f1 = __half22float2(h1);
    return make_float4(f0.x, f0.y, f1.x, f1.y);
}

// ================= flat-dispatch batched fp16 HMMA GEMM =================
#define KC 64
#define TILE_B 16384
#define STAGE_B (2 * TILE_B)
#define GEMM_SMEM (2 * STAGE_B)

struct GemmJob {
    float* C; __half* Ch; int ldc; int Nvalid;
    const __half* A1; const __half* B1; int K1;
    const __half* A2; const __half* B2; int K2;
    const float* bias; int do_relu; int bx;
};

__device__ __forceinline__ void issue_chunk(
    uint32_t sb_stage,
    const __half* A, const __half* B,
    int ldA, int ldB, int rowBase, int colBase, int k0, int tid)
{
#pragma unroll
    for (int t = 0; t < 2; ++t) {
        const __half* src = (t == 0) ? A : B;
        const int row0 = (t == 0) ? rowBase : colBase;
        const int ld = (t == 0) ? ldA : ldB;
        const uint32_t tb = sb_stage + t * TILE_B;
#pragma unroll
        for (int i = 0; i < 4; ++i) {
            int idx = i * 256 + tid;
            int r = idx >> 3;
            int cch = idx & 7;
            uint32_t dst = tb + r * 128 + (((cch ^ (r & 7))) << 4);
            cp16(dst, src + (size_t)(row0 + r) * ld + k0 + cch * 8);
        }
    }
}

__global__ __launch_bounds__(256, 2) void mma_gemm(
    GemmJob j0, GemmJob j1, GemmJob j2, int n0, int n1)
{
    const int bid = blockIdx.x;
    GemmJob j;
    int rel;
    if (bid < n0)      { j = j0; rel = bid; }
    else if (bid < n1) { j = j1; rel = bid - n0; }
    else               { j = j2; rel = bid - n1; }

    extern __shared__ char smem[];
    const uint32_t sb = smem_u32(smem);
    const int tid = threadIdx.x;
    const int wid = tid >> 5;
    const int lane = tid & 31;
    const int warp_m = wid & 3;
    const int warp_n = wid >> 2;
    const int rowBase = (rel / j.bx) * 128;
    const int colBase = (rel % j.bx) * 128;

    float c[2][8][4];
#pragma unroll
    for (int i = 0; i < 2; ++i)
#pragma unroll
        for (int jn = 0; jn < 8; ++jn)
#pragma unroll
            for (int k = 0; k < 4; ++k) c[i][jn][k] = 0.f;

    const int NC1 = j.K1 / KC;
    const int NC2 = j.K2 / KC;
    const int NC = NC1 + NC2;

    issue_chunk(sb, j.A1, j.B1, j.K1, j.K1, rowBase, colBase, 0, tid);
    cp_commit();

#pragma unroll 1
    for (int ch = 0; ch < NC; ++ch) {
        const uint32_t cur = sb + (uint32_t)(ch & 1) * STAGE_B;
        if (ch + 1 < NC) {
            int nc = ch + 1;
            if (nc < NC1)
                issue_chunk(sb + (uint32_t)(nc & 1) * STAGE_B, j.A1, j.B1,
                            j.K1, j.K1, rowBase, colBase, nc * KC, tid);
            else
                issue_chunk(sb + (uint32_t)(nc & 1) * STAGE_B, j.A2, j.B2,
                            j.K2, j.K2, rowBase, colBase, (nc - NC1) * KC, tid);
            cp_commit();
            asm volatile("cp.async.wait_group 1;" ::: "memory");
        } else {
            cp_wait_all();
        }
        __syncthreads();

#pragma unroll
        for (int ks = 0; ks < 4; ++ks) {
            uint32_t ah[2][4], bh[4][4];
#pragma unroll
            for (int mf = 0; mf < 2; ++mf) {
                int row = warp_m * 32 + mf * 16 + ((lane >> 3) & 1) * 8 + (lane & 7);
                int chunk = ks * 2 + (lane >> 4);
                uint32_t ad = cur + row * 128 + ((chunk ^ (row & 7)) << 4);
                ldmx4(ah[mf], ad);
            }
#pragma unroll
            for (int nf2 = 0; nf2 < 4; ++nf2) {
                int row = warp_n * 64 + nf2 * 16 + (lane >> 4) * 8 + (lane & 7);
                int chunk = ks * 2 + ((lane >> 3) & 1);
                uint32_t bd = cur + TILE_B + row * 128 + ((chunk ^ (row & 7)) << 4);
                ldmx4(bh[nf2], bd);
            }
#pragma unroll
            for (int mf = 0; mf < 2; ++mf)
#pragma unroll
                for (int nf = 0; nf < 8; ++nf)
                    mma_f16(c[mf][nf], ah[mf], &bh[nf >> 1][(nf & 1) * 2]);
        }
        __syncthreads();
    }

    const int r0 = rowBase + warp_m * 32 + (lane >> 2);
    const int colb = colBase + warp_n * 64 + (lane & 3) * 2;
#pragma unroll
    for (int mf = 0; mf < 2; ++mf) {
        int row = r0 + mf * 16;
#pragma unroll
        for (int nf = 0; nf < 8; ++nf) {
            int col = colb + nf * 8;
            if (col < j.Nvalid) {
                float b0 = 0.f, b1 = 0.f;
                if (j.bias) { b0 = j.bias[col]; b1 = j.bias[col + 1]; }
                float2 v0, v1;
                v0.x = c[mf][nf][0] + b0; v0.y = c[mf][nf][1] + b1;
                v1.x = c[mf][nf][2] + b0; v1.y = c[mf][nf][3] + b1;
                if (j.do_relu) {
                    v0.x = fmaxf(v0.x, 0.f); v0.y = fmaxf(v0.y, 0.f);
                    v1.x = fmaxf(v1.x, 0.f); v1.y = fmaxf(v1.y, 0.f);
                }
                if (j.Ch) {
                    __half2 h0 = __floats2half2_rn(v0.x, v0.y);
                    __half2 h1 = __floats2half2_rn(v1.x, v1.y);
                    *(__half2*)(j.Ch + (size_t)row * j.ldc + col) = h0;
                    *(__half2*)(j.Ch + (size_t)(row + 8) * j.ldc + col) = h1;
                } else {
                    *(float2*)(j.C + (size_t)row * j.ldc + col) = v0;
                    *(float2*)(j.C + (size_t)(row + 8) * j.ldc + col) = v1;
                }
            }
        }
    }
}

// ================= conversion kernels (also zeroes g_cnt + WsT pad; pads s_f) =================
__global__ void round_rows2(const float* __restrict__ a, __half* __restrict__ ah,
                            const float* __restrict__ b, __half* __restrict__ bh,
                            const float* __restrict__ sf, __half* __restrict__ sfp) {
    const size_t T1 = (size_t)N_NODES * 1024;
    const size_t T2 = (size_t)N_NODES * 320;
    const size_t T3 = (size_t)N_EDGES * 64;
    size_t gid = (size_t)blockIdx.x * blockDim.x + threadIdx.x;
    size_t stride = (size_t)gridDim.x * blockDim.x;
    for (size_t i = gid; i < (size_t)N_NODES; i += stride) g_cnt[i] = 0;
    for (size_t i = gid; i < (size_t)1024 * 64; i += stride) g_WsT_h[i] = __float2half_rn(0.f);
    for (size_t i = gid; i < T1 + T2 + T3; i += stride) {
        if (i < T1) {
            ah[i] = __float2half_rn(a[i]);
        } else if (i < T1 + T2) {
            size_t jj = i - T1;
            int row = (int)(jj / 320);
            int col = (int)(jj % 320);
            float v = (col < 300) ? b[(size_t)row * 300 + col] : 0.f;
            bh[jj] = __float2half_rn(v);
        } else {
            size_t jj = i - T1 - T2;
            int row = (int)(jj >> 6);
            int col = (int)(jj & 63);
            float v = (col < 16) ? sf[(size_t)row * 16 + col] : 0.f;
            sfp[jj] = __float2half_rn(v);
        }
    }
}

__global__ void transpose_round2(const float* __restrict__ W0, const float* __restrict__ W1,
                                 int ldw, int K, int N,
                                 __half* __restrict__ hi, int Kd, int n0_0, int n0_1) {
    const float* W = blockIdx.z ? W1 : W0;
    const int n0 = blockIdx.z ? n0_1 : n0_0;
    __shared__ float tile[32][33];
    int kb = blockIdx.y * 32, nb = blockIdx.x * 32;
#pragma unroll
    for (int i = 0; i < 4; ++i) {
        int k = kb + threadIdx.y + i * 8;
        int n = nb + threadIdx.x;
        tile[threadIdx.y + i * 8][threadIdx.x] = (k < K && n < N) ? W[(size_t)k * ldw + n] : 0.f;
    }
    __syncthreads();
#pragma unroll
    for (int i = 0; i < 4; ++i) {
        int n = nb + threadIdx.y + i * 8;
        int k = kb + threadIdx.x;
        if (n < N && k < Kd)
            hi[(size_t)(n0 + n) * Kd + k] = __float2half_rn(tile[threadIdx.x][threadIdx.y + i * 8]);
    }
}

// ================= CSR construction =================
__global__ void hist_kernel(const int* __restrict__ dst) {
    int e = blockIdx.x * blockDim.x + threadIdx.x;
    if (e < N_EDGES) atomicAdd(&g_cnt[dst[e]], 1);
}
__global__ __launch_bounds__(1024) void scan_kernel() {
    __shared__ int sm[1024];
    int t = threadIdx.x;
    int loc[8];
    int s = 0;
#pragma unroll
    for (int i = 0; i < 8; ++i) { loc[i] = g_cnt[t * 8 + i]; s += loc[i]; }
    sm[t] = s;
    __syncthreads();
    for (int off = 1; off < 1024; off <<= 1) {
        int v = sm[t];
        if (t >= off) v += sm[t - off];
        __syncthreads();
        sm[t] = v;
        __syncthreads();
    }
    int run = (t == 0) ? 0 : sm[t - 1];
#pragma unroll
    for (int i = 0; i < 8; ++i) {
        g_off[t * 8 + i] = run;
        g_fill[t * 8 + i] = run;
        run += loc[i];
    }
}
__global__ void fill_kernel(const int* __restrict__ dst) {
    int e = blockIdx.x * blockDim.x + threadIdx.x;
    if (e < N_EDGES) {
        int pos = atomicAdd(&g_fill[dst[e]], 1);
        g_eid[pos] = e;
    }
}

// ================= merged score+softmax+combine kernel =================
#define COMB_SMEM ((2 * CACHE_E * 1024 + CACHE_E * 320) * 2)

__global__ __launch_bounds__(256, 3) void combine_all(
    const int* __restrict__ src,
    const float* __restrict__ be, const float* __restrict__ Wa,
    const float* __restrict__ bel, const float* __restrict__ Wal)
{
    extern __shared__ __half dyn[];
    __half* efc = dyn;                       // P rows -> e_f
    __half* nfc = dyn + CACHE_E * 1024;      // S rows -> nf rows
    __half* wvc = dyn + 2 * CACHE_E * 1024;
    const uint32_t efc_b = smem_u32(efc);
    const uint32_t nfc_b = smem_u32(nfc);
    const uint32_t wvc_b = smem_u32(wvc);

    const int d = blockIdx.x;
    const int t = threadIdx.x;
    const int lane = t & 31;
    const int deg = g_cnt[d];
    const int start = g_off[d];
    const int cdeg = (deg < CACHE_E) ? deg : CACHE_E;

    __shared__ int sm_eid[MAXDEG], sm_src[MAXDEG];
    __shared__ float sm_af[MAXDEG], sm_afl[MAXDEG];
    __shared__ float sm_scal[4];

    for (int i = t; i < deg; i += 256) {
        int e = g_eid[start + i];
        sm_eid[i] = e;
        sm_src[i] = src[e];
    }
    for (int i = t; i < MAXDEG; i += 256) { sm_af[i] = 0.f; sm_afl[i] = 0.f; }
    __syncthreads();

    // ---------- Phase A0: bulk-gather P1[src] rows and S[eid] rows ----------
#pragma unroll 1
    for (int i = 0; i < cdeg; ++i) {
        cp8(efc_b + (uint32_t)(i * 1024 + 4 * t) * 2,
            g_P_h + (size_t)sm_src[i] * 2048 + 4 * t);
        cp8(nfc_b + (uint32_t)(i * 1024 + 4 * t) * 2,
            g_S_h + (size_t)sm_eid[i] * 1024 + 4 * t);
    }
    cp_commit();

    float4 p3r;
    {
        uint2 pr = *(const uint2*)(g_P_h + (size_t)d * 2048 + 1024 + 4 * t);
        p3r = h4_to_f4(pr);
        float4 ber = ((const float4*)be)[t];
        p3r.x += ber.x; p3r.y += ber.y; p3r.z += ber.z; p3r.w += ber.w;
    }
    float4 war = ((const float4*)Wa)[t];
    float4 q2r = make_float4(0.f, 0.f, 0.f, 0.f);
    float4 walr = make_float4(0.f, 0.f, 0.f, 0.f);
    if (t < 150) {
        uint2 qr = *(const uint2*)(g_Q_h + (size_t)d * 1200 + 600 + 4 * t);
        q2r = h4_to_f4(qr);
        float4 belr = ((const float4*)bel)[t];
        q2r.x += belr.x; q2r.y += belr.y; q2r.z += belr.z; q2r.w += belr.w;
        walr = ((const float4*)Wal)[t];
    }

    cp_wait_all();
    __syncthreads();

    // ---------- Phase A: e_f + scores ----------
    uint2 qr_c = make_uint2(0u, 0u);
    if (deg > 0 && t < 150)
        qr_c = *(const uint2*)(g_Q_h + (size_t)sm_src[0] * 1200 + 4 * t);

#pragma unroll 1
    for (int i = 0; i < deg; ++i) {
        uint2 qr_n = make_uint2(0u, 0u);
        if (i + 1 < deg && t < 150)
            qr_n = *(const uint2*)(g_Q_h + (size_t)sm_src[i + 1] * 1200 + 4 * t);

        float4 v;
        if (i < CACHE_E) {
            float4 p = h4_to_f4(*(const uint2*)(efc + i * 1024 + 4 * t));
            float4 s = h4_to_f4(*(const uint2*)(nfc + i * 1024 + 4 * t));
            v.x = p.x + s.x + p3r.x; v.y = p.y + s.y + p3r.y;
            v.z = p.z + s.z + p3r.z; v.w = p.w + s.w + p3r.w;
        } else {
            float4 p = h4_to_f4(*(const uint2*)(g_P_h + (size_t)sm_src[i] * 2048 + 4 * t));
            float4 s = h4_to_f4(*(const uint2*)(g_S_h + (size_t)sm_eid[i] * 1024 + 4 * t));
            v.x = p.x + s.x + p3r.x; v.y = p.y + s.y + p3r.y;
            v.z = p.z + s.z + p3r.z; v.w = p.w + s.w + p3r.w;
        }
        v.x = fmaxf(v.x, 0.f); v.y = fmaxf(v.y, 0.f);
        v.z = fmaxf(v.z, 0.f); v.w = fmaxf(v.w, 0.f);
        if (i < CACHE_E) {
            __half2 h0 = __floats2half2_rn(v.x, v.y);
            __half2 h1 = __floats2half2_rn(v.z, v.w);
            uint2 pk;
            pk.x = *(uint32_t*)&h0;
            pk.y = *(uint32_t*)&h1;
            *(uint2*)(efc + i * 1024 + 4 * t) = pk;   // e_f replaces P row
        }

        float acc = v.x * war.x + v.y * war.y + v.z * war.z + v.w * war.w;

        float accl = 0.f;
        if (t < 150) {
            float4 u = h4_to_f4(qr_c);
            u.x = fmaxf(u.x + q2r.x, 0.f); u.y = fmaxf(u.y + q2r.y, 0.f);
            u.z = fmaxf(u.z + q2r.z, 0.f); u.w = fmaxf(u.w + q2r.w, 0.f);
            accl = u.x * walr.x + u.y * walr.y + u.z * walr.z + u.w * walr.w;
        }

#pragma unroll
        for (int off = 16; off > 0; off >>= 1) {
            acc += __shfl_down_sync(0xffffffffu, acc, off);
            accl += __shfl_down_sync(0xffffffffu, accl, off);
        }
        if (lane == 0) {
            atomicAdd(&sm_af[i], acc);
            if (accl != 0.f) atomicAdd(&sm_afl[i], accl);
        }
        qr_c = qr_n;
    }

    // ---------- Phase B0: bulk-gather nf / w2v rows (overlaps softmax) ----------
#pragma unroll 1
    for (int i = 0; i < cdeg; ++i) {
        int s = sm_src[i];
        cp8(nfc_b + (uint32_t)(i * 1024 + 4 * t) * 2,
            g_nf_h + (size_t)s * 1024 + 4 * t);
        if (t < 75)
            cp8(wvc_b + (uint32_t)(i * 320 + 4 * t) * 2,
                g_w2v_h + (size_t)s * 320 + 4 * t);
    }
    cp_commit();
    __syncthreads();

    // ---------- softmax scalars (warp 0) ----------
    if (t < 32) {
        float m = -1e30f, ml = -1e30f;
        for (int i = t; i < deg; i += 32) {
            m = fmaxf(m, sm_af[i]);
            ml = fmaxf(ml, sm_afl[i]);
        }
#pragma unroll
        for (int off = 16; off > 0; off >>= 1) {
            m = fmaxf(m, __shfl_xor_sync(0xffffffffu, m, off));
            ml = fmaxf(ml, __shfl_xor_sync(0xffffffffu, ml, off));
        }
        float den = 0.f, denl = 0.f;
        for (int i = t; i < deg; i += 32) {
            den += expf(sm_af[i] - m);
            denl += expf(sm_afl[i] - ml);
        }
#pragma unroll
        for (int off = 16; off > 0; off >>= 1) {
            den += __shfl_xor_sync(0xffffffffu, den, off);
            denl += __shfl_xor_sync(0xffffffffu, denl, off);
        }
        if (t == 0) {
            sm_scal[0] = m;
            sm_scal[1] = (deg > 0) ? 1.f / den : 0.f;
            sm_scal[2] = ml;
            sm_scal[3] = (deg > 0) ? 1.f / denl : 0.f;
        }
    }
    __syncthreads();

    {
        const float m = sm_scal[0], rden = sm_scal[1];
        const float ml = sm_scal[2], rdenl = sm_scal[3];
        for (int i = t; i < deg; i += 256) {
            sm_af[i] = expf(sm_af[i] - m) * rden;
            sm_afl[i] = expf(sm_afl[i] - ml) * rdenl;
        }
    }
    cp_wait_all();
    __syncthreads();

    // ---------- Phase B: weighted accumulate ----------
    float4 acc = make_float4(0.f, 0.f, 0.f, 0.f);
    float4 accl = make_float4(0.f, 0.f, 0.f, 0.f);

#pragma unroll 1
    for (int i = 0; i < deg; ++i) {
        const float alpha = sm_af[i];
        const float alphal = sm_afl[i];

        float4 v, n;
        if (i < CACHE_E) {
            v = h4_to_f4(*(const uint2*)(efc + i * 1024 + 4 * t));
            n = h4_to_f4(*(const uint2*)(nfc + i * 1024 + 4 * t));
        } else {
            const int s = sm_src[i];
            float4 p = h4_to_f4(*(const uint2*)(g_P_h + (size_t)s * 2048 + 4 * t));
            float4 sr = h4_to_f4(*(const uint2*)(g_S_h + (size_t)sm_eid[i] * 1024 + 4 * t));
            v.x = fmaxf(p.x + sr.x + p3r.x, 0.f);
            v.y = fmaxf(p.y + sr.y + p3r.y, 0.f);
            v.z = fmaxf(p.z + sr.z + p3r.z, 0.f);
            v.w = fmaxf(p.w + sr.w + p3r.w, 0.f);
            n = h4_to_f4(*(const uint2*)(g_nf_h + (size_t)s * 1024 + 4 * t));
        }

        acc.x = fmaf(alpha, n.x + v.x, acc.x);
        acc.y = fmaf(alpha, n.y + v.y, acc.y);
        acc.z = fmaf(alpha, n.z + v.z, acc.z);
        acc.w = fmaf(alpha, n.w + v.w, acc.w);

        if (t < 75) {
            float4 w;
            if (i < CACHE_E)
                w = h4_to_f4(*(const uint2*)(wvc + i * 320 + 4 * t));
            else
                w = h4_to_f4(*(const uint2*)(g_w2v_h + (size_t)sm_src[i] * 320 + 4 * t));
            accl.x = fmaf(alphal, w.x, accl.x);
            accl.y = fmaf(alphal, w.y, accl.y);
            accl.z = fmaf(alphal, w.z, accl.z);
            accl.w = fmaf(alphal, w.w, accl.w);
        }
    }

    // ---------- write fp16 ----------
    {
        size_t o = (size_t)d * 1024 + 4 * t;
        g_zf_h[o + 0] = __float2half_rn(acc.x);
        g_zf_h[o + 1] = __float2half_rn(acc.y);
        g_zf_h[o + 2] = __float2half_rn(acc.z);
        g_zf_h[o + 3] = __float2half_rn(acc.w);
    }
    if (t < 75) {
        size_t o = (size_t)d * 320 + 4 * t;
        g_zfl_h[o + 0] = __float2half_rn(accl.x);
        g_zfl_h[o + 1] = __float2half_rn(accl.y);
        g_zfl_h[o + 2] = __float2half_rn(accl.z);
        g_zfl_h[o + 3] = __float2half_rn(accl.w);
    }
}

// ================= launch =================
extern "C" void kernel_launch(void* const* d_in, const int* in_sizes, int n_in,
                              void* d_out, int out_size) {
    const float* n_f  = (const float*)d_in[0];
    const float* w2v  = (const float*)d_in[1];
    const float* s_f  = (const float*)d_in[2];
    const int*   src  = (const int*)d_in[3];
    const int*   dst  = (const int*)d_in[4];
    const float* We   = (const float*)d_in[5];
    const float* be   = (const float*)d_in[6];
    const float* Wel  = (const float*)d_in[7];
    const float* bel  = (const float*)d_in[8];
    const float* Wa   = (const float*)d_in[9];
    const float* Wal  = (const float*)d_in[11];
    const float* Wn   = (const float*)d_in[13];
    const float* bn   = (const float*)d_in[14];
    const float* Wnl  = (const float*)d_in[15];
    const float* bnl  = (const float*)d_in[16];

    float* out      = (float*)d_out;
    float* out_lang = out + (size_t)N_NODES * 1024;

    __half *P_h, *Q_h, *S_h, *sfp_h, *WsT_h;
    __half *nf_h, *w2v_h, *zf_h, *zfl_h;
    __half *WeT_h, *WnT_h, *WelT_h, *WnlT_h;
    cudaGetSymbolAddress((void**)&P_h, g_P_h);
    cudaGetSymbolAddress((void**)&Q_h, g_Q_h);
    cudaGetSymbolAddress((void**)&S_h, g_S_h);
    cudaGetSymbolAddress((void**)&sfp_h, g_sfp_h);
    cudaGetSymbolAddress((void**)&WsT_h, g_WsT_h);
    cudaGetSymbolAddress((void**)&nf_h, g_nf_h);
    cudaGetSymbolAddress((void**)&w2v_h, g_w2v_h);
    cudaGetSymbolAddress((void**)&zf_h, g_zf_h);
    cudaGetSymbolAddress((void**)&zfl_h, g_zfl_h);
    cudaGetSymbolAddress((void**)&WeT_h, g_WeT_h);
    cudaGetSymbolAddress((void**)&WnT_h, g_WnT_h);
    cudaGetSymbolAddress((void**)&WelT_h, g_WelT_h);
    cudaGetSymbolAddress((void**)&WnlT_h, g_WnlT_h);

    cudaFuncSetAttribute(mma_gemm, cudaFuncAttributeMaxDynamicSharedMemorySize, GEMM_SMEM);
    cudaFuncSetAttribute(combine_all, cudaFuncAttributeMaxDynamicSharedMemorySize, COMB_SMEM);

    dim3 tblk(32, 8);

    round_rows2<<<2048, 256>>>(n_f, nf_h, w2v, w2v_h, s_f, sfp_h);   // zeroes g_cnt + WsT too
    transpose_round2<<<dim3(32, 32, 2), tblk>>>(We, We + (size_t)1040 * 1024,
                                                1024, 1024, 1024, WeT_h, 1024, 0, 1024);
    transpose_round2<<<dim3(32, 1, 1), tblk>>>(We + (size_t)1024 * 1024, nullptr,
                                               1024, 16, 1024, WsT_h, 64, 0, 0);
    transpose_round2<<<dim3(19, 10, 2), tblk>>>(Wel, Wel + (size_t)300 * 600,
                                                600, 300, 600, WelT_h, 320, 0, 600);
    hist_kernel<<<64, 1024>>>(dst);
    scan_kernel<<<1, 1024>>>();
    fill_kernel<<<64, 1024>>>(dst);

    // merged projections + edge S GEMM in ONE launch (flat dispatch)
    {
        GemmJob jp = {nullptr, P_h, 2048, 2048, nf_h, WeT_h, 1024,
                      nullptr, nullptr, 0, nullptr, 0, 16};   // 16 x 64 = 1024 blocks
        GemmJob jq = {nullptr, Q_h, 1200, 1200, w2v_h, WelT_h, 320,
                      nullptr, nullptr, 0, nullptr, 0, 10};   // 10 x 64 = 640 blocks
        GemmJob js = {nullptr, S_h, 1024, 1024, sfp_h, WsT_h, 64,
                      nullptr, nullptr, 0, nullptr, 0, 8};    // 8 x 512 = 4096 blocks
        int n0 = 16 * 64;
        int n1 = n0 + 10 * 64;
        int total = n1 + 8 * 512;
        mma_gemm<<<total, 256, GEMM_SMEM>>>(jp, jq, js, n0, n1);
    }

    transpose_round2<<<dim3(32, 32, 2), tblk>>>(Wn, Wn + (size_t)1024 * 1024,
                                                1024, 1024, 1024, WnT_h, 1024, 0, 1024);
    transpose_round2<<<dim3(10, 10, 2), tblk>>>(Wnl, Wnl + (size_t)300 * 300,
                                                300, 300, 300, WnlT_h, 320, 0, 300);

    combine_all<<<N_NODES, 256, COMB_SMEM>>>(src, be, Wa, bel, Wal);

    // merged node-apply GEMMs in ONE launch
    {
        GemmJob jo = {out, nullptr, 1024, 1024, nf_h, WnT_h, 1024,
                      zf_h, WnT_h + (size_t)1024 * 1024, 1024, bn, 1, 8};   // 8 x 64 = 512
        GemmJob jl = {out_lang, nullptr, 300, 300, w2v_h, WnlT_h, 320,
                      zfl_h, WnlT_h + (size_t)300 * 320, 320, bnl, 1, 3};   // 3 x 64 = 192
        int n0 = 8 * 64;
        int total = n0 + 3 * 64;
        mma_gemm<<<total, 256, GEMM_SMEM>>>(jo, jl, jl, n0, total);
    }
}